// round 14
// baseline (speedup 1.0000x reference)
#include <cuda_runtime.h>
#include <cuda_fp16.h>

// ---------------------------------------------------------------------------
// GAT encoder, R13: aggregate-then-GEMM restructure.
//   L1: als1 = x·(W1 a)_h ; aggx[d,h,:] = softmax-agg of x rows (4 heads,
//       x row loaded once per edge); agg1 = aggx_h @ W1_h + b1, relu.
//   L2: als2 = agg1·(W2 a); agghx[d,:] = softmax-agg of agg1 rows (128-dim,
//       HALF the bytes of gathering hlin2); out = agghx @ W2 + b2.
// Gathers remain warp-per-node MLP=4 (R6-verified shape). CSR on s2.
// ---------------------------------------------------------------------------

#define NNODES 50000
#define EMAX   1700000

__device__ __align__(16) __half g_xh[NNODES * 128];
__device__ __align__(16) __half g_wt1h[128 * 128];      // W1^T [n][k]
__device__ __align__(16) __half g_wt2h[256 * 128];      // W2^T [n][k]
__device__ __align__(16) float  g_wa1s[4 * 128];        // (W1 a_src1)_h [h][k]
__device__ __align__(16) float  g_wa1d[4 * 128];
__device__ __align__(16) float  g_wa2s[128];
__device__ __align__(16) float  g_wa2d[128];
__device__ __align__(16) float  g_als1[NNODES * 4];
__device__ __align__(16) float  g_ald1[NNODES * 4];
__device__ __align__(16) __half g_aggx[NNODES * 512];   // [n][h][k] fp16
__device__ __align__(16) __half g_agg1h[NNODES * 128];  // layer1 out fp16
__device__ __align__(16) float  g_als2[NNODES];
__device__ __align__(16) float  g_ald2[NNODES];
__device__ __align__(16) __half g_agghx[NNODES * 128];  // layer2 aggregate fp16
__device__ int g_count[NNODES];
__device__ int g_rowstart[NNODES + 1];
__device__ int g_cursor[NNODES];
__device__ int g_sorted_src[EMAX];

__device__ __forceinline__ float lrelu(float x) {
    return x > 0.0f ? x : 0.2f * x;
}

// ---------------------------------------------------------------------------
// Conversions + attention-weight folding
// ---------------------------------------------------------------------------
__global__ void cvt_f2h(const float* __restrict__ in, __half* __restrict__ out, int n4) {
    int i = blockIdx.x * blockDim.x + threadIdx.x;
    if (i >= n4) return;
    float4 v = *(const float4*)&in[i * 4];
    __half2 h0 = __floats2half2_rn(v.x, v.y);
    __half2 h1 = __floats2half2_rn(v.z, v.w);
    uint2 u;
    u.x = *(unsigned int*)&h0;
    u.y = *(unsigned int*)&h1;
    *(uint2*)&out[i * 4] = u;
}

__global__ void cvt_wts(const float* __restrict__ W1, __half* __restrict__ WT1,
                        const float* __restrict__ W2, __half* __restrict__ WT2) {
    int i = blockIdx.x * blockDim.x + threadIdx.x;
    if (i < 128 * 128) {
        int n = i >> 7, k = i & 127;
        WT1[i] = __float2half(W1[k * 128 + n]);
    } else if (i < 128 * 128 + 256 * 128) {
        int j = i - 128 * 128;
        int n = j >> 7, k = j & 127;
        WT2[j] = __float2half(W2[k * 256 + n]);
    }
}

// wa1s[h][k] = sum_c W1[k][h*32+c]*as1[h*32+c]; wa2s[k] = sum_c W2[k][c]*as2[c]
__global__ __launch_bounds__(512, 1)
void cvt_wa(const float* __restrict__ W1,
            const float* __restrict__ as1, const float* __restrict__ ad1,
            const float* __restrict__ W2,
            const float* __restrict__ as2, const float* __restrict__ ad2,
            float* __restrict__ wa1s, float* __restrict__ wa1d,
            float* __restrict__ wa2s, float* __restrict__ wa2d) {
    int t = threadIdx.x;
    {
        int h = t >> 7, k = t & 127;
        float s = 0.f, d = 0.f;
        #pragma unroll 8
        for (int c = 0; c < 32; c++) {
            float w = W1[k * 128 + h * 32 + c];
            s = fmaf(w, as1[h * 32 + c], s);
            d = fmaf(w, ad1[h * 32 + c], d);
        }
        wa1s[h * 128 + k] = s;
        wa1d[h * 128 + k] = d;
    }
    if (t < 128) {
        int k = t;
        float s = 0.f, d = 0.f;
        #pragma unroll 8
        for (int c = 0; c < 256; c++) {
            float w = W2[k * 256 + c];
            s = fmaf(w, as2[c], s);
            d = fmaf(w, ad2[c], d);
        }
        wa2s[k] = s;
        wa2d[k] = d;
    }
}

// ---------------------------------------------------------------------------
// CSR build (vectorized; self-loops folded into scan).
// ---------------------------------------------------------------------------
__global__ void hist_dst_v(const int* __restrict__ ei, int E,
                           int* __restrict__ cnt) {
    int i = blockIdx.x * blockDim.x + threadIdx.x;
    int nv = E >> 2;
    if (i < nv) {
        int4 d4 = *(const int4*)&ei[E + i * 4];
        atomicAdd(&cnt[d4.x], 1);
        atomicAdd(&cnt[d4.y], 1);
        atomicAdd(&cnt[d4.z], 1);
        atomicAdd(&cnt[d4.w], 1);
    } else {
        int e = nv * 4 + (i - nv);
        if (e < E) atomicAdd(&cnt[ei[E + e]], 1);
    }
}

__global__ __launch_bounds__(1024, 1)
void scan_counts(const int* __restrict__ cnt, int* __restrict__ rowstart,
                 int* __restrict__ cursor, int N) {
    __shared__ int wsum[32];
    __shared__ int s_carry;
    const int tid = threadIdx.x, lane = tid & 31, wid = tid >> 5;
    if (tid == 0) s_carry = 0;
    __syncthreads();
    for (int base = 0; base < N; base += 4096) {
        int idx = base + tid * 4;
        int4 v = make_int4(-1, -1, -1, -1);
        if (idx + 3 < N) v = *(const int4*)&cnt[idx];
        else {
            if (idx + 0 < N) v.x = cnt[idx + 0];
            if (idx + 1 < N) v.y = cnt[idx + 1];
            if (idx + 2 < N) v.z = cnt[idx + 2];
            if (idx + 3 < N) v.w = cnt[idx + 3];
        }
        v.x += 1; v.y += 1; v.z += 1; v.w += 1;
        int tsum = v.x + v.y + v.z + v.w;
        int x = tsum;
        #pragma unroll
        for (int off = 1; off < 32; off <<= 1) {
            int y = __shfl_up_sync(0xFFFFFFFFu, x, off);
            if (lane >= off) x += y;
        }
        if (lane == 31) wsum[wid] = x;
        __syncthreads();
        if (wid == 0) {
            int w = wsum[lane];
            #pragma unroll
            for (int off = 1; off < 32; off <<= 1) {
                int y = __shfl_up_sync(0xFFFFFFFFu, w, off);
                if (lane >= off) w += y;
            }
            wsum[lane] = w;
        }
        __syncthreads();
        int carry = s_carry;
        int excl = carry + (wid > 0 ? wsum[wid - 1] : 0) + x - tsum;
        int e0 = excl, e1 = e0 + v.x, e2 = e1 + v.y, e3 = e2 + v.z;
        if (idx + 3 < N) {
            *(int4*)&rowstart[idx] = make_int4(e0, e1, e2, e3);
            *(int4*)&cursor[idx]   = make_int4(e0, e1, e2, e3);
        } else {
            if (idx + 0 < N) { rowstart[idx + 0] = e0; cursor[idx + 0] = e0; }
            if (idx + 1 < N) { rowstart[idx + 1] = e1; cursor[idx + 1] = e1; }
            if (idx + 2 < N) { rowstart[idx + 2] = e2; cursor[idx + 2] = e2; }
            if (idx + 3 < N) { rowstart[idx + 3] = e3; cursor[idx + 3] = e3; }
        }
        __syncthreads();
        if (tid == 1023) s_carry = carry + wsum[31];
        __syncthreads();
    }
    if (tid == 0) rowstart[N] = s_carry;
}

__global__ void scatter_edges_v(const int* __restrict__ ei, int E, int N,
                                int* __restrict__ cursor,
                                int* __restrict__ sorted_src) {
    int i = blockIdx.x * blockDim.x + threadIdx.x;
    int nv = E >> 2;
    if (i < nv) {
        int4 s4 = *(const int4*)&ei[i * 4];
        int4 d4 = *(const int4*)&ei[E + i * 4];
        int p0 = atomicAdd(&cursor[d4.x], 1);
        int p1 = atomicAdd(&cursor[d4.y], 1);
        int p2 = atomicAdd(&cursor[d4.z], 1);
        int p3 = atomicAdd(&cursor[d4.w], 1);
        sorted_src[p0] = s4.x;
        sorted_src[p1] = s4.y;
        sorted_src[p2] = s4.z;
        sorted_src[p3] = s4.w;
    } else if (i < nv + N) {
        int d = i - nv;
        int p = atomicAdd(&cursor[d], 1);
        sorted_src[p] = d;
    } else {
        int e = nv * 4 + (i - nv - N);
        if (e < E) {
            int s = ei[e], d = ei[E + e];
            int p = atomicAdd(&cursor[d], 1);
            sorted_src[p] = s;
        }
    }
}

// ---------------------------------------------------------------------------
// Attention-term kernels (warp per node, full-warp dot)
// ---------------------------------------------------------------------------
__global__ __launch_bounds__(256)
void als1_k(const __half* __restrict__ xh,
            const float* __restrict__ wa1s, const float* __restrict__ wa1d,
            float* __restrict__ als, float* __restrict__ ald, int N) {
    int w = (blockIdx.x * blockDim.x + threadIdx.x) >> 5;
    int lane = threadIdx.x & 31;
    if (w >= N) return;
    uint2 raw = *(const uint2*)&xh[(size_t)w * 128 + lane * 4];
    float2 f0 = __half22float2(*(const __half2*)&raw.x);
    float2 f1 = __half22float2(*(const __half2*)&raw.y);
    float ps0, ps1, ps2, ps3, pd0, pd1, pd2, pd3;
    {
        float4 s = *(const float4*)&wa1s[0 * 128 + lane * 4];
        float4 d = *(const float4*)&wa1d[0 * 128 + lane * 4];
        ps0 = f0.x * s.x + f0.y * s.y + f1.x * s.z + f1.y * s.w;
        pd0 = f0.x * d.x + f0.y * d.y + f1.x * d.z + f1.y * d.w;
    }
    {
        float4 s = *(const float4*)&wa1s[1 * 128 + lane * 4];
        float4 d = *(const float4*)&wa1d[1 * 128 + lane * 4];
        ps1 = f0.x * s.x + f0.y * s.y + f1.x * s.z + f1.y * s.w;
        pd1 = f0.x * d.x + f0.y * d.y + f1.x * d.z + f1.y * d.w;
    }
    {
        float4 s = *(const float4*)&wa1s[2 * 128 + lane * 4];
        float4 d = *(const float4*)&wa1d[2 * 128 + lane * 4];
        ps2 = f0.x * s.x + f0.y * s.y + f1.x * s.z + f1.y * s.w;
        pd2 = f0.x * d.x + f0.y * d.y + f1.x * d.z + f1.y * d.w;
    }
    {
        float4 s = *(const float4*)&wa1s[3 * 128 + lane * 4];
        float4 d = *(const float4*)&wa1d[3 * 128 + lane * 4];
        ps3 = f0.x * s.x + f0.y * s.y + f1.x * s.z + f1.y * s.w;
        pd3 = f0.x * d.x + f0.y * d.y + f1.x * d.z + f1.y * d.w;
    }
    #pragma unroll
    for (int off = 16; off > 0; off >>= 1) {
        ps0 += __shfl_xor_sync(0xFFFFFFFFu, ps0, off);
        ps1 += __shfl_xor_sync(0xFFFFFFFFu, ps1, off);
        ps2 += __shfl_xor_sync(0xFFFFFFFFu, ps2, off);
        ps3 += __shfl_xor_sync(0xFFFFFFFFu, ps3, off);
        pd0 += __shfl_xor_sync(0xFFFFFFFFu, pd0, off);
        pd1 += __shfl_xor_sync(0xFFFFFFFFu, pd1, off);
        pd2 += __shfl_xor_sync(0xFFFFFFFFu, pd2, off);
        pd3 += __shfl_xor_sync(0xFFFFFFFFu, pd3, off);
    }
    if (lane == 0) {
        *(float4*)&als[w * 4] = make_float4(ps0, ps1, ps2, ps3);
        *(float4*)&ald[w * 4] = make_float4(pd0, pd1, pd2, pd3);
    }
}

__global__ __launch_bounds__(256)
void als2_k(const __half* __restrict__ h,
            const float* __restrict__ wa2s, const float* __restrict__ wa2d,
            float* __restrict__ als, float* __restrict__ ald, int N) {
    int w = (blockIdx.x * blockDim.x + threadIdx.x) >> 5;
    int lane = threadIdx.x & 31;
    if (w >= N) return;
    uint2 raw = *(const uint2*)&h[(size_t)w * 128 + lane * 4];
    float2 f0 = __half22float2(*(const __half2*)&raw.x);
    float2 f1 = __half22float2(*(const __half2*)&raw.y);
    float4 s = *(const float4*)&wa2s[lane * 4];
    float4 d = *(const float4*)&wa2d[lane * 4];
    float ps = f0.x * s.x + f0.y * s.y + f1.x * s.z + f1.y * s.w;
    float pd = f0.x * d.x + f0.y * d.y + f1.x * d.z + f1.y * d.w;
    #pragma unroll
    for (int off = 16; off > 0; off >>= 1) {
        ps += __shfl_xor_sync(0xFFFFFFFFu, ps, off);
        pd += __shfl_xor_sync(0xFFFFFFFFu, pd, off);
    }
    if (lane == 0) { als[w] = ps; ald[w] = pd; }
}

// ---------------------------------------------------------------------------
// Layer-1 gather of x rows, 4 head-aggregates from one load. MLP=4.
// aggx[n][h][k] fp16 = normalized per-head aggregate.
// ---------------------------------------------------------------------------
__global__ __launch_bounds__(256)
void gather_x(const int* __restrict__ rowstart, const int* __restrict__ ssrc,
              const float* __restrict__ als, const float* __restrict__ ald,
              const __half* __restrict__ xh, __half* __restrict__ aggx, int N) {
    int w = (blockIdx.x * blockDim.x + threadIdx.x) >> 5;
    int lane = threadIdx.x & 31;
    if (w >= N) return;
    const int beg = rowstart[w];
    const int end = rowstart[w + 1];
    const float4 ad = *(const float4*)&ald[w * 4];

    float4 ssum = make_float4(0.f, 0.f, 0.f, 0.f);
    float4 a0 = make_float4(0.f, 0.f, 0.f, 0.f);   // head 0, 4 channels
    float4 a1 = make_float4(0.f, 0.f, 0.f, 0.f);
    float4 a2 = make_float4(0.f, 0.f, 0.f, 0.f);
    float4 a3 = make_float4(0.f, 0.f, 0.f, 0.f);

    #define DO_EDGE(asv, rv)                                                   \
    {                                                                          \
        float e0 = __expf(lrelu(asv.x + ad.x));                                \
        float e1 = __expf(lrelu(asv.y + ad.y));                                \
        float e2 = __expf(lrelu(asv.z + ad.z));                                \
        float e3 = __expf(lrelu(asv.w + ad.w));                                \
        ssum.x += e0; ssum.y += e1; ssum.z += e2; ssum.w += e3;                \
        float2 q0 = __half22float2(*(const __half2*)&rv.x);                    \
        float2 q1 = __half22float2(*(const __half2*)&rv.y);                    \
        a0.x = fmaf(e0, q0.x, a0.x); a0.y = fmaf(e0, q0.y, a0.y);              \
        a0.z = fmaf(e0, q1.x, a0.z); a0.w = fmaf(e0, q1.y, a0.w);              \
        a1.x = fmaf(e1, q0.x, a1.x); a1.y = fmaf(e1, q0.y, a1.y);              \
        a1.z = fmaf(e1, q1.x, a1.z); a1.w = fmaf(e1, q1.y, a1.w);              \
        a2.x = fmaf(e2, q0.x, a2.x); a2.y = fmaf(e2, q0.y, a2.y);              \
        a2.z = fmaf(e2, q1.x, a2.z); a2.w = fmaf(e2, q1.y, a2.w);              \
        a3.x = fmaf(e3, q0.x, a3.x); a3.y = fmaf(e3, q0.y, a3.y);              \
        a3.z = fmaf(e3, q1.x, a3.z); a3.w = fmaf(e3, q1.y, a3.w);              \
    }

    int j = beg;
    for (; j + 4 <= end; j += 4) {
        int sn0 = ssrc[j], sn1 = ssrc[j + 1], sn2 = ssrc[j + 2], sn3 = ssrc[j + 3];
        float4 as0 = *(const float4*)&als[sn0 * 4];
        float4 as1 = *(const float4*)&als[sn1 * 4];
        float4 as2 = *(const float4*)&als[sn2 * 4];
        float4 as3 = *(const float4*)&als[sn3 * 4];
        uint2 r0 = *(const uint2*)&xh[(size_t)sn0 * 128 + lane * 4];
        uint2 r1 = *(const uint2*)&xh[(size_t)sn1 * 128 + lane * 4];
        uint2 r2 = *(const uint2*)&xh[(size_t)sn2 * 128 + lane * 4];
        uint2 r3 = *(const uint2*)&xh[(size_t)sn3 * 128 + lane * 4];
        DO_EDGE(as0, r0)
        DO_EDGE(as1, r1)
        DO_EDGE(as2, r2)
        DO_EDGE(as3, r3)
    }
    for (; j < end; j++) {
        int sn = ssrc[j];
        float4 asv = *(const float4*)&als[sn * 4];
        uint2 rv = *(const uint2*)&xh[(size_t)sn * 128 + lane * 4];
        DO_EDGE(asv, rv)
    }
    #undef DO_EDGE

    __half* op = &aggx[(size_t)w * 512 + lane * 4];
    {
        float inv = 1.0f / (ssum.x + 1e-16f);
        __half2 h0 = __floats2half2_rn(a0.x * inv, a0.y * inv);
        __half2 h1 = __floats2half2_rn(a0.z * inv, a0.w * inv);
        uint2 u; u.x = *(unsigned int*)&h0; u.y = *(unsigned int*)&h1;
        *(uint2*)&op[0] = u;
    }
    {
        float inv = 1.0f / (ssum.y + 1e-16f);
        __half2 h0 = __floats2half2_rn(a1.x * inv, a1.y * inv);
        __half2 h1 = __floats2half2_rn(a1.z * inv, a1.w * inv);
        uint2 u; u.x = *(unsigned int*)&h0; u.y = *(unsigned int*)&h1;
        *(uint2*)&op[128] = u;
    }
    {
        float inv = 1.0f / (ssum.z + 1e-16f);
        __half2 h0 = __floats2half2_rn(a2.x * inv, a2.y * inv);
        __half2 h1 = __floats2half2_rn(a2.z * inv, a2.w * inv);
        uint2 u; u.x = *(unsigned int*)&h0; u.y = *(unsigned int*)&h1;
        *(uint2*)&op[256] = u;
    }
    {
        float inv = 1.0f / (ssum.w + 1e-16f);
        __half2 h0 = __floats2half2_rn(a3.x * inv, a3.y * inv);
        __half2 h1 = __floats2half2_rn(a3.z * inv, a3.w * inv);
        uint2 u; u.x = *(unsigned int*)&h0; u.y = *(unsigned int*)&h1;
        *(uint2*)&op[384] = u;
    }
}

// ---------------------------------------------------------------------------
// Layer-2 gather of agg1 rows (128-dim, single alpha). MLP=4. fp16 out.
// ---------------------------------------------------------------------------
__global__ __launch_bounds__(256)
void gather_h1(const int* __restrict__ rowstart, const int* __restrict__ ssrc,
               const float* __restrict__ als, const float* __restrict__ ald,
               const __half* __restrict__ h1, __half* __restrict__ outp, int N) {
    int w = (blockIdx.x * blockDim.x + threadIdx.x) >> 5;
    int lane = threadIdx.x & 31;
    if (w >= N) return;
    const int beg = rowstart[w];
    const int end = rowstart[w + 1];
    const float ad = ald[w];

    float ssum = 0.f;
    float4 acc = make_float4(0.f, 0.f, 0.f, 0.f);

    int j = beg;
    for (; j + 4 <= end; j += 4) {
        int sn0 = ssrc[j], sn1 = ssrc[j + 1], sn2 = ssrc[j + 2], sn3 = ssrc[j + 3];
        float al0 = als[sn0], al1 = als[sn1], al2 = als[sn2], al3 = als[sn3];
        uint2 r0 = *(const uint2*)&h1[(size_t)sn0 * 128 + lane * 4];
        uint2 r1 = *(const uint2*)&h1[(size_t)sn1 * 128 + lane * 4];
        uint2 r2 = *(const uint2*)&h1[(size_t)sn2 * 128 + lane * 4];
        uint2 r3 = *(const uint2*)&h1[(size_t)sn3 * 128 + lane * 4];
        float e0 = __expf(lrelu(al0 + ad));
        float e1 = __expf(lrelu(al1 + ad));
        float e2 = __expf(lrelu(al2 + ad));
        float e3 = __expf(lrelu(al3 + ad));
        ssum += (e0 + e1) + (e2 + e3);
        float2 a, b;
        a = __half22float2(*(const __half2*)&r0.x);
        b = __half22float2(*(const __half2*)&r0.y);
        acc.x = fmaf(e0, a.x, acc.x); acc.y = fmaf(e0, a.y, acc.y);
        acc.z = fmaf(e0, b.x, acc.z); acc.w = fmaf(e0, b.y, acc.w);
        a = __half22float2(*(const __half2*)&r1.x);
        b = __half22float2(*(const __half2*)&r1.y);
        acc.x = fmaf(e1, a.x, acc.x); acc.y = fmaf(e1, a.y, acc.y);
        acc.z = fmaf(e1, b.x, acc.z); acc.w = fmaf(e1, b.y, acc.w);
        a = __half22float2(*(const __half2*)&r2.x);
        b = __half22float2(*(const __half2*)&r2.y);
        acc.x = fmaf(e2, a.x, acc.x); acc.y = fmaf(e2, a.y, acc.y);
        acc.z = fmaf(e2, b.x, acc.z); acc.w = fmaf(e2, b.y, acc.w);
        a = __half22float2(*(const __half2*)&r3.x);
        b = __half22float2(*(const __half2*)&r3.y);
        acc.x = fmaf(e3, a.x, acc.x); acc.y = fmaf(e3, a.y, acc.y);
        acc.z = fmaf(e3, b.x, acc.z); acc.w = fmaf(e3, b.y, acc.w);
    }
    for (; j < end; j++) {
        int sn = ssrc[j];
        float e = __expf(lrelu(als[sn] + ad));
        uint2 r = *(const uint2*)&h1[(size_t)sn * 128 + lane * 4];
        ssum += e;
        float2 a = __half22float2(*(const __half2*)&r.x);
        float2 b = __half22float2(*(const __half2*)&r.y);
        acc.x = fmaf(e, a.x, acc.x); acc.y = fmaf(e, a.y, acc.y);
        acc.z = fmaf(e, b.x, acc.z); acc.w = fmaf(e, b.y, acc.w);
    }
    const float inv = 1.0f / (ssum + 1e-16f);
    __half2 h0 = __floats2half2_rn(acc.x * inv, acc.y * inv);
    __half2 h1o = __floats2half2_rn(acc.z * inv, acc.w * inv);
    uint2 u;
    u.x = *(unsigned int*)&h0;
    u.y = *(unsigned int*)&h1o;
    *(uint2*)&outp[(size_t)w * 128 + lane * 4] = u;
}

// ---------------------------------------------------------------------------
// GEMM1 per head: agg1[:, h*32..+32] = aggx[:,h,:]@W1h + b1, relu. fp16 out.
// Block 128Mx32N, 8 warps (8M), warp tile 16x32.
// ---------------------------------------------------------------------------
#define AS_STRIDE 40
#define BS_STRIDE 136

__device__ __forceinline__ void mma16816(float* c, const unsigned int* a,
                                         unsigned int b0, unsigned int b1) {
    asm volatile(
        "mma.sync.aligned.m16n8k16.row.col.f32.f16.f16.f32 "
        "{%0,%1,%2,%3}, {%4,%5,%6,%7}, {%8,%9}, {%0,%1,%2,%3};"
        : "+f"(c[0]), "+f"(c[1]), "+f"(c[2]), "+f"(c[3])
        : "r"(a[0]), "r"(a[1]), "r"(a[2]), "r"(a[3]), "r"(b0), "r"(b1));
}

__global__ __launch_bounds__(256, 1)
void hgemm_head(const __half* __restrict__ aggx, const __half* __restrict__ WT1,
                const float* __restrict__ b1, __half* __restrict__ C, int M) {
    __shared__ __half As[128 * AS_STRIDE];
    __shared__ __half Bs[32 * BS_STRIDE];

    const int tid  = threadIdx.x;
    const int lane = tid & 31;
    const int wid  = tid >> 5;
    const int row0 = blockIdx.x * 128;
    const int head = blockIdx.y;
    const int wm = wid * 16;

    {
        int n = tid >> 3;              // 0..31
        int p = (tid & 7) * 16;        // 0..112
        const uint4* src = (const uint4*)&WT1[(size_t)(head * 32 + n) * 128 + p];
        uint4* dst = (uint4*)&Bs[n * BS_STRIDE + p];
        dst[0] = src[0]; dst[1] = src[1];
    }

    float acc[4][4];
    #pragma unroll
    for (int nt = 0; nt < 4; nt++)
        #pragma unroll
        for (int q = 0; q < 4; q++) acc[nt][q] = 0.0f;

    const int arow = tid >> 1;
    const int acol = (tid & 1) * 16;
    const int frow = lane >> 2;
    const int fcol = 2 * (lane & 3);

    for (int kc = 0; kc < 128; kc += 32) {
        uint4 v0 = make_uint4(0, 0, 0, 0), v1 = make_uint4(0, 0, 0, 0);
        int gr = row0 + arow;
        if (gr < M) {
            const uint4* s = (const uint4*)&aggx[(size_t)gr * 512 + head * 128 + kc + acol];
            v0 = s[0]; v1 = s[1];
        }
        __syncthreads();
        *(uint4*)&As[arow * AS_STRIDE + acol]     = v0;
        *(uint4*)&As[arow * AS_STRIDE + acol + 8] = v1;
        __syncthreads();

        #pragma unroll
        for (int kk = 0; kk < 32; kk += 16) {
            unsigned int a[4];
            int r = wm + frow;
            int c = kk + fcol;
            a[0] = *(const unsigned int*)&As[r * AS_STRIDE + c];
            a[1] = *(const unsigned int*)&As[(r + 8) * AS_STRIDE + c];
            a[2] = *(const unsigned int*)&As[r * AS_STRIDE + c + 8];
            a[3] = *(const unsigned int*)&As[(r + 8) * AS_STRIDE + c + 8];
            #pragma unroll
            for (int nt = 0; nt < 4; nt++) {
                int n = nt * 8 + frow;
                int ck = kc + kk + fcol;
                unsigned int b0 = *(const unsigned int*)&Bs[n * BS_STRIDE + ck];
                unsigned int b1v = *(const unsigned int*)&Bs[n * BS_STRIDE + ck + 8];
                mma16816(acc[nt], a, b0, b1v);
            }
        }
    }

    #pragma unroll
    for (int nt = 0; nt < 4; nt++) {
        int c = head * 32 + nt * 8 + fcol;
        float2 bb = *(const float2*)&b1[c];
        int r = row0 + wm + frow;
        if (r < M) {
            float v0 = fmaxf(acc[nt][0] + bb.x, 0.f);
            float v1 = fmaxf(acc[nt][1] + bb.y, 0.f);
            *(__half2*)&C[(size_t)r * 128 + c] = __floats2half2_rn(v0, v1);
        }
        if (r + 8 < M) {
            float v0 = fmaxf(acc[nt][2] + bb.x, 0.f);
            float v1 = fmaxf(acc[nt][3] + bb.y, 0.f);
            *(__half2*)&C[(size_t)(r + 8) * 128 + c] = __floats2half2_rn(v0, v1);
        }
    }
}

// ---------------------------------------------------------------------------
// GEMM2: out[N,256] fp32 = agghx[N,128] @ W2 + b2.
// Block 128x64, 8 warps (4M x 2N), warp tile 32x32.
// ---------------------------------------------------------------------------
__global__ __launch_bounds__(256, 1)
void hgemm_f32out(const __half* __restrict__ A, const __half* __restrict__ WT,
                  const float* __restrict__ bias, float* __restrict__ C,
                  int M, int Ncols) {
    __shared__ __half As[128 * AS_STRIDE];
    __shared__ __half Bs[64 * BS_STRIDE];

    const int tid  = threadIdx.x;
    const int lane = tid & 31;
    const int wid  = tid >> 5;
    const int row0 = blockIdx.x * 128;
    const int col0 = blockIdx.y * 64;
    const int wm = (wid & 3) * 32;
    const int wn = (wid >> 2) * 32;

    {
        int n = tid >> 2;
        int p = (tid & 3) * 32;
        const uint4* src = (const uint4*)&WT[(size_t)(col0 + n) * 128 + p];
        uint4* dst = (uint4*)&Bs[n * BS_STRIDE + p];
        dst[0] = src[0]; dst[1] = src[1]; dst[2] = src[2]; dst[3] = src[3];
    }

    float acc[2][4][4];
    #pragma unroll
    for (int mt = 0; mt < 2; mt++)
        #pragma unroll
        for (int nt = 0; nt < 4; nt++)
            #pragma unroll
            for (int q = 0; q < 4; q++) acc[mt][nt][q] = 0.0f;

    const int arow = tid >> 1;
    const int acol = (tid & 1) * 16;
    const int frow = lane >> 2;
    const int fcol = 2 * (lane & 3);

    for (int kc = 0; kc < 128; kc += 32) {
        uint4 v0 = make_uint4(0, 0, 0, 0), v1 = make_uint4(0, 0, 0, 0);
        int gr = row0 + arow;
        if (gr < M) {
            const uint4* s = (const uint4*)&A[(size_t)gr * 128 + kc + acol];
            v0 = s[0]; v1 = s[1];
        }
        __syncthreads();
        *(uint4*)&As[arow * AS_STRIDE + acol]     = v0;
        *(uint4*)&As[arow * AS_STRIDE + acol + 8] = v1;
        __syncthreads();

        #pragma unroll
        for (int kk = 0; kk < 32; kk += 16) {
            unsigned int a[2][4];
            #pragma unroll
            for (int mt = 0; mt < 2; mt++) {
                int r = wm + mt * 16 + frow;
                int c = kk + fcol;
                a[mt][0] = *(const unsigned int*)&As[r * AS_STRIDE + c];
                a[mt][1] = *(const unsigned int*)&As[(r + 8) * AS_STRIDE + c];
                a[mt][2] = *(const unsigned int*)&As[r * AS_STRIDE + c + 8];
                a[mt][3] = *(const unsigned int*)&As[(r + 8) * AS_STRIDE + c + 8];
            }
            #pragma unroll
            for (int nt = 0; nt < 4; nt++) {
                int n = wn + nt * 8 + frow;
                int ck = kc + kk + fcol;
                unsigned int b0 = *(const unsigned int*)&Bs[n * BS_STRIDE + ck];
                unsigned int b1 = *(const unsigned int*)&Bs[n * BS_STRIDE + ck + 8];
                mma16816(acc[0][nt], a[0], b0, b1);
                mma16816(acc[1][nt], a[1], b0, b1);
            }
        }
    }

    #pragma unroll
    for (int mt = 0; mt < 2; mt++) {
        int r = row0 + wm + mt * 16 + frow;
        #pragma unroll
        for (int nt = 0; nt < 4; nt++) {
            int c = col0 + wn + nt * 8 + fcol;
            float2 bb = *(const float2*)&bias[c];
            if (r < M) {
                float2 v = make_float2(acc[mt][nt][0] + bb.x, acc[mt][nt][1] + bb.y);
                *(float2*)&C[(size_t)r * Ncols + c] = v;
            }
            if (r + 8 < M) {
                float2 v = make_float2(acc[mt][nt][2] + bb.x, acc[mt][nt][3] + bb.y);
                *(float2*)&C[(size_t)(r + 8) * Ncols + c] = v;
            }
        }
    }
}

// ---------------------------------------------------------------------------
// Launch
// ---------------------------------------------------------------------------
extern "C" void kernel_launch(void* const* d_in, const int* in_sizes, int n_in,
                              void* d_out, int out_size) {
    const float* x   = (const float*)d_in[0];
    const int*   ei  = (const int*)d_in[1];
    const float* W1  = (const float*)d_in[2];
    const float* as1 = (const float*)d_in[3];
    const float* ad1 = (const float*)d_in[4];
    const float* b1  = (const float*)d_in[5];
    const float* W2  = (const float*)d_in[6];
    const float* as2 = (const float*)d_in[7];
    const float* ad2 = (const float*)d_in[8];
    const float* b2  = (const float*)d_in[9];
    float* out = (float*)d_out;

    const int N = in_sizes[0] / 128;   // 50000
    const int E = in_sizes[1] / 2;     // 1600000

    float *wa1s, *wa1d, *wa2s, *wa2d, *als1p, *ald1p, *als2p, *ald2p;
    __half *xh, *wt1h, *wt2h, *aggx, *agg1h, *agghx;
    int *cntp, *rowp, *curp, *ssrcp;
    cudaGetSymbolAddress((void**)&xh,    g_xh);
    cudaGetSymbolAddress((void**)&wt1h,  g_wt1h);
    cudaGetSymbolAddress((void**)&wt2h,  g_wt2h);
    cudaGetSymbolAddress((void**)&wa1s,  g_wa1s);
    cudaGetSymbolAddress((void**)&wa1d,  g_wa1d);
    cudaGetSymbolAddress((void**)&wa2s,  g_wa2s);
    cudaGetSymbolAddress((void**)&wa2d,  g_wa2d);
    cudaGetSymbolAddress((void**)&als1p, g_als1);
    cudaGetSymbolAddress((void**)&ald1p, g_ald1);
    cudaGetSymbolAddress((void**)&aggx,  g_aggx);
    cudaGetSymbolAddress((void**)&agg1h, g_agg1h);
    cudaGetSymbolAddress((void**)&als2p, g_als2);
    cudaGetSymbolAddress((void**)&ald2p, g_ald2);
    cudaGetSymbolAddress((void**)&agghx, g_agghx);
    cudaGetSymbolAddress((void**)&cntp,  g_count);
    cudaGetSymbolAddress((void**)&rowp,  g_rowstart);
    cudaGetSymbolAddress((void**)&curp,  g_cursor);
    cudaGetSymbolAddress((void**)&ssrcp, g_sorted_src);

    static cudaStream_t s2 = nullptr;
    static cudaEvent_t ev_fork = nullptr, ev_csr = nullptr;
    if (s2 == nullptr) {
        cudaStreamCreateWithFlags(&s2, cudaStreamNonBlocking);
        cudaEventCreateWithFlags(&ev_fork, cudaEventDisableTiming);
        cudaEventCreateWithFlags(&ev_csr,  cudaEventDisableTiming);
    }

    const int NW_BLOCKS = (N * 32 + 255) / 256;
    const int HIST_THREADS = (E >> 2) + (E & 3);
    const int SCAT_THREADS = (E >> 2) + N + (E & 3);

    // --- fork: CSR build on s2 ---
    cudaEventRecord(ev_fork, 0);
    cudaStreamWaitEvent(s2, ev_fork, 0);
    cudaMemsetAsync(cntp, 0, (size_t)N * sizeof(int), s2);
    hist_dst_v<<<(HIST_THREADS + 255) / 256, 256, 0, s2>>>(ei, E, cntp);
    scan_counts<<<1, 1024, 0, s2>>>(cntp, rowp, curp, N);
    scatter_edges_v<<<(SCAT_THREADS + 255) / 256, 256, 0, s2>>>(ei, E, N, curp, ssrcp);
    cudaEventRecord(ev_csr, s2);

    // --- main: conversions + folded attention weights + als1 ---
    cvt_f2h<<<(N * 128 / 4 + 255) / 256, 256>>>(x, xh, N * 128 / 4);
    cvt_wts<<<(128 * 128 + 256 * 128 + 255) / 256, 256>>>(W1, wt1h, W2, wt2h);
    cvt_wa<<<1, 512>>>(W1, as1, ad1, W2, as2, ad2, wa1s, wa1d, wa2s, wa2d);
    als1_k<<<NW_BLOCKS, 256>>>(xh, wa1s, wa1d, als1p, ald1p, N);

    // --- join CSR; layer 1: gather x -> per-head GEMM ---
    cudaStreamWaitEvent(0, ev_csr, 0);
    gather_x<<<NW_BLOCKS, 256>>>(rowp, ssrcp, als1p, ald1p, xh, aggx, N);
    {
        dim3 grid((N + 127) / 128, 4);
        hgemm_head<<<grid, 256>>>(aggx, wt1h, b1, agg1h, N);
    }

    // --- layer 2: als2 -> gather agg1 (128-dim!) -> GEMM2 ---
    als2_k<<<NW_BLOCKS, 256>>>(agg1h, wa2s, wa2d, als2p, ald2p, N);
    gather_h1<<<NW_BLOCKS, 256>>>(rowp, ssrcp, als2p, ald2p, agg1h, agghx, N);
    {
        dim3 grid((N + 127) / 128, 4);
        hgemm_f32out<<<grid, 256>>>(agghx, wt2h, b2, out, N, 256);
    }
}

// round 15
// speedup vs baseline: 1.3792x; 1.3792x over previous
#include <cuda_runtime.h>
#include <cuda_fp16.h>

// ---------------------------------------------------------------------------
// GAT encoder, R14 hybrid:
//   Layer 1 = verified 241.6us path: cvt -> HMMA GEMM1 -> node_alpha1 ->
//             fused gather (fp16 agg1 out, bias+relu).
//   Layer 2 = aggregate-before-GEMM: als2 = agg1·(W2 a2) (folded),
//             gather 128-dim agg1 rows (HALF the bytes of gathering hlin2),
//             then GEMM2 (+bias) -> fp32 out. hlin2 never materializes.
// CSR build (vectorized) on stream s2.
// ---------------------------------------------------------------------------

#define NNODES 50000
#define EMAX   1700000

__device__ __align__(16) __half g_xh[NNODES * 128];
__device__ __align__(16) __half g_wt1h[128 * 128];
__device__ __align__(16) __half g_wt2h[256 * 128];
__device__ __align__(16) float  g_wa2s[128];
__device__ __align__(16) float  g_wa2d[128];
__device__ __align__(16) __half g_hlin1[NNODES * 128];
__device__ __align__(16) float  g_als1[NNODES * 4];
__device__ __align__(16) float  g_ald1[NNODES * 4];
__device__ __align__(16) __half g_agg1h[NNODES * 128];
__device__ __align__(16) float  g_als2[NNODES];
__device__ __align__(16) float  g_ald2[NNODES];
__device__ __align__(16) __half g_agghx[NNODES * 128];
__device__ int g_count[NNODES];
__device__ int g_rowstart[NNODES + 1];
__device__ int g_cursor[NNODES];
__device__ int g_sorted_src[EMAX];

__device__ __forceinline__ float lrelu(float x) {
    return x > 0.0f ? x : 0.2f * x;
}

// ---------------------------------------------------------------------------
// Conversions
// ---------------------------------------------------------------------------
__global__ void cvt_f2h(const float* __restrict__ in, __half* __restrict__ out, int n4) {
    int i = blockIdx.x * blockDim.x + threadIdx.x;
    if (i >= n4) return;
    float4 v = *(const float4*)&in[i * 4];
    __half2 h0 = __floats2half2_rn(v.x, v.y);
    __half2 h1 = __floats2half2_rn(v.z, v.w);
    uint2 u;
    u.x = *(unsigned int*)&h0;
    u.y = *(unsigned int*)&h1;
    *(uint2*)&out[i * 4] = u;
}

__global__ void cvt_wts(const float* __restrict__ W1, __half* __restrict__ WT1,
                        const float* __restrict__ W2, __half* __restrict__ WT2) {
    int i = blockIdx.x * blockDim.x + threadIdx.x;
    if (i < 128 * 128) {
        int n = i >> 7, k = i & 127;
        WT1[i] = __float2half(W1[k * 128 + n]);
    } else if (i < 128 * 128 + 256 * 128) {
        int j = i - 128 * 128;
        int n = j >> 7, k = j & 127;
        WT2[j] = __float2half(W2[k * 256 + n]);
    }
}

// wa2s[k] = sum_c W2[k][c]*as2[c]  (and same for ad2)
__global__ __launch_bounds__(128, 1)
void cvt_wa2(const float* __restrict__ W2,
             const float* __restrict__ as2, const float* __restrict__ ad2,
             float* __restrict__ wa2s, float* __restrict__ wa2d) {
    int k = threadIdx.x;
    float s = 0.f, d = 0.f;
    #pragma unroll 8
    for (int c = 0; c < 256; c++) {
        float w = W2[k * 256 + c];
        s = fmaf(w, as2[c], s);
        d = fmaf(w, ad2[c], d);
    }
    wa2s[k] = s;
    wa2d[k] = d;
}

// ---------------------------------------------------------------------------
// CSR build (vectorized; self-loops folded into scan).
// ---------------------------------------------------------------------------
__global__ void hist_dst_v(const int* __restrict__ ei, int E,
                           int* __restrict__ cnt) {
    int i = blockIdx.x * blockDim.x + threadIdx.x;
    int nv = E >> 2;
    if (i < nv) {
        int4 d4 = *(const int4*)&ei[E + i * 4];
        atomicAdd(&cnt[d4.x], 1);
        atomicAdd(&cnt[d4.y], 1);
        atomicAdd(&cnt[d4.z], 1);
        atomicAdd(&cnt[d4.w], 1);
    } else {
        int e = nv * 4 + (i - nv);
        if (e < E) atomicAdd(&cnt[ei[E + e]], 1);
    }
}

__global__ __launch_bounds__(1024, 1)
void scan_counts(const int* __restrict__ cnt, int* __restrict__ rowstart,
                 int* __restrict__ cursor, int N) {
    __shared__ int wsum[32];
    __shared__ int s_carry;
    const int tid = threadIdx.x, lane = tid & 31, wid = tid >> 5;
    if (tid == 0) s_carry = 0;
    __syncthreads();
    for (int base = 0; base < N; base += 4096) {
        int idx = base + tid * 4;
        int4 v = make_int4(-1, -1, -1, -1);
        if (idx + 3 < N) v = *(const int4*)&cnt[idx];
        else {
            if (idx + 0 < N) v.x = cnt[idx + 0];
            if (idx + 1 < N) v.y = cnt[idx + 1];
            if (idx + 2 < N) v.z = cnt[idx + 2];
            if (idx + 3 < N) v.w = cnt[idx + 3];
        }
        v.x += 1; v.y += 1; v.z += 1; v.w += 1;
        int tsum = v.x + v.y + v.z + v.w;
        int x = tsum;
        #pragma unroll
        for (int off = 1; off < 32; off <<= 1) {
            int y = __shfl_up_sync(0xFFFFFFFFu, x, off);
            if (lane >= off) x += y;
        }
        if (lane == 31) wsum[wid] = x;
        __syncthreads();
        if (wid == 0) {
            int w = wsum[lane];
            #pragma unroll
            for (int off = 1; off < 32; off <<= 1) {
                int y = __shfl_up_sync(0xFFFFFFFFu, w, off);
                if (lane >= off) w += y;
            }
            wsum[lane] = w;
        }
        __syncthreads();
        int carry = s_carry;
        int excl = carry + (wid > 0 ? wsum[wid - 1] : 0) + x - tsum;
        int e0 = excl, e1 = e0 + v.x, e2 = e1 + v.y, e3 = e2 + v.z;
        if (idx + 3 < N) {
            *(int4*)&rowstart[idx] = make_int4(e0, e1, e2, e3);
            *(int4*)&cursor[idx]   = make_int4(e0, e1, e2, e3);
        } else {
            if (idx + 0 < N) { rowstart[idx + 0] = e0; cursor[idx + 0] = e0; }
            if (idx + 1 < N) { rowstart[idx + 1] = e1; cursor[idx + 1] = e1; }
            if (idx + 2 < N) { rowstart[idx + 2] = e2; cursor[idx + 2] = e2; }
            if (idx + 3 < N) { rowstart[idx + 3] = e3; cursor[idx + 3] = e3; }
        }
        __syncthreads();
        if (tid == 1023) s_carry = carry + wsum[31];
        __syncthreads();
    }
    if (tid == 0) rowstart[N] = s_carry;
}

__global__ void scatter_edges_v(const int* __restrict__ ei, int E, int N,
                                int* __restrict__ cursor,
                                int* __restrict__ sorted_src) {
    int i = blockIdx.x * blockDim.x + threadIdx.x;
    int nv = E >> 2;
    if (i < nv) {
        int4 s4 = *(const int4*)&ei[i * 4];
        int4 d4 = *(const int4*)&ei[E + i * 4];
        int p0 = atomicAdd(&cursor[d4.x], 1);
        int p1 = atomicAdd(&cursor[d4.y], 1);
        int p2 = atomicAdd(&cursor[d4.z], 1);
        int p3 = atomicAdd(&cursor[d4.w], 1);
        sorted_src[p0] = s4.x;
        sorted_src[p1] = s4.y;
        sorted_src[p2] = s4.z;
        sorted_src[p3] = s4.w;
    } else if (i < nv + N) {
        int d = i - nv;
        int p = atomicAdd(&cursor[d], 1);
        sorted_src[p] = d;
    } else {
        int e = nv * 4 + (i - nv - N);
        if (e < E) {
            int s = ei[e], d = ei[E + e];
            int p = atomicAdd(&cursor[d], 1);
            sorted_src[p] = s;
        }
    }
}

// ---------------------------------------------------------------------------
// HGEMM (fp16 C): C_h[M,Ncols] = A_h[M,128] @ WT. (layer-1 GEMM, exact R6)
// ---------------------------------------------------------------------------
#define AS_STRIDE 40
#define BS_STRIDE 136

__device__ __forceinline__ void mma16816(float* c, const unsigned int* a,
                                         unsigned int b0, unsigned int b1) {
    asm volatile(
        "mma.sync.aligned.m16n8k16.row.col.f32.f16.f16.f32 "
        "{%0,%1,%2,%3}, {%4,%5,%6,%7}, {%8,%9}, {%0,%1,%2,%3};"
        : "+f"(c[0]), "+f"(c[1]), "+f"(c[2]), "+f"(c[3])
        : "r"(a[0]), "r"(a[1]), "r"(a[2]), "r"(a[3]), "r"(b0), "r"(b1));
}

__global__ __launch_bounds__(256, 1)
void hgemm_k128(const __half* __restrict__ A, const __half* __restrict__ WT,
                __half* __restrict__ C, int M, int Ncols) {
    __shared__ __half As[128 * AS_STRIDE];
    __shared__ __half Bs[64 * BS_STRIDE];

    const int tid  = threadIdx.x;
    const int lane = tid & 31;
    const int wid  = tid >> 5;
    const int row0 = blockIdx.x * 128;
    const int col0 = blockIdx.y * 64;
    const int wm = (wid & 3) * 32;
    const int wn = (wid >> 2) * 32;

    {
        int n = tid >> 2;
        int p = (tid & 3) * 32;
        const uint4* src = (const uint4*)&WT[(size_t)(col0 + n) * 128 + p];
        uint4* dst = (uint4*)&Bs[n * BS_STRIDE + p];
        dst[0] = src[0]; dst[1] = src[1]; dst[2] = src[2]; dst[3] = src[3];
    }

    float acc[2][4][4];
    #pragma unroll
    for (int mt = 0; mt < 2; mt++)
        #pragma unroll
        for (int nt = 0; nt < 4; nt++)
            #pragma unroll
            for (int q = 0; q < 4; q++) acc[mt][nt][q] = 0.0f;

    const int arow = tid >> 1;
    const int acol = (tid & 1) * 16;
    const int frow = lane >> 2;
    const int fcol = 2 * (lane & 3);

    for (int kc = 0; kc < 128; kc += 32) {
        uint4 v0 = make_uint4(0, 0, 0, 0), v1 = make_uint4(0, 0, 0, 0);
        int gr = row0 + arow;
        if (gr < M) {
            const uint4* s = (const uint4*)&A[(size_t)gr * 128 + kc + acol];
            v0 = s[0]; v1 = s[1];
        }
        __syncthreads();
        *(uint4*)&As[arow * AS_STRIDE + acol]     = v0;
        *(uint4*)&As[arow * AS_STRIDE + acol + 8] = v1;
        __syncthreads();

        #pragma unroll
        for (int kk = 0; kk < 32; kk += 16) {
            unsigned int a[2][4];
            #pragma unroll
            for (int mt = 0; mt < 2; mt++) {
                int r = wm + mt * 16 + frow;
                int c = kk + fcol;
                a[mt][0] = *(const unsigned int*)&As[r * AS_STRIDE + c];
                a[mt][1] = *(const unsigned int*)&As[(r + 8) * AS_STRIDE + c];
                a[mt][2] = *(const unsigned int*)&As[r * AS_STRIDE + c + 8];
                a[mt][3] = *(const unsigned int*)&As[(r + 8) * AS_STRIDE + c + 8];
            }
            #pragma unroll
            for (int nt = 0; nt < 4; nt++) {
                int n = wn + nt * 8 + frow;
                int ck = kc + kk + fcol;
                unsigned int b0 = *(const unsigned int*)&Bs[n * BS_STRIDE + ck];
                unsigned int b1 = *(const unsigned int*)&Bs[n * BS_STRIDE + ck + 8];
                mma16816(acc[0][nt], a[0], b0, b1);
                mma16816(acc[1][nt], a[1], b0, b1);
            }
        }
    }

    #pragma unroll
    for (int mt = 0; mt < 2; mt++) {
        int r = row0 + wm + mt * 16 + frow;
        #pragma unroll
        for (int nt = 0; nt < 4; nt++) {
            int c = col0 + wn + nt * 8 + fcol;
            if (r < M) {
                __half2 h = __floats2half2_rn(acc[mt][nt][0], acc[mt][nt][1]);
                *(__half2*)&C[(size_t)r * Ncols + c] = h;
            }
            if (r + 8 < M) {
                __half2 h = __floats2half2_rn(acc[mt][nt][2], acc[mt][nt][3]);
                *(__half2*)&C[(size_t)(r + 8) * Ncols + c] = h;
            }
        }
    }
}

// ---------------------------------------------------------------------------
// HGEMM (fp32 C + bias): out[M,Ncols] = A_h[M,128] @ WT + bias. (layer-2 GEMM)
// ---------------------------------------------------------------------------
__global__ __launch_bounds__(256, 1)
void hgemm_f32out(const __half* __restrict__ A, const __half* __restrict__ WT,
                  const float* __restrict__ bias, float* __restrict__ C,
                  int M, int Ncols) {
    __shared__ __half As[128 * AS_STRIDE];
    __shared__ __half Bs[64 * BS_STRIDE];

    const int tid  = threadIdx.x;
    const int lane = tid & 31;
    const int wid  = tid >> 5;
    const int row0 = blockIdx.x * 128;
    const int col0 = blockIdx.y * 64;
    const int wm = (wid & 3) * 32;
    const int wn = (wid >> 2) * 32;

    {
        int n = tid >> 2;
        int p = (tid & 3) * 32;
        const uint4* src = (const uint4*)&WT[(size_t)(col0 + n) * 128 + p];
        uint4* dst = (uint4*)&Bs[n * BS_STRIDE + p];
        dst[0] = src[0]; dst[1] = src[1]; dst[2] = src[2]; dst[3] = src[3];
    }

    float acc[2][4][4];
    #pragma unroll
    for (int mt = 0; mt < 2; mt++)
        #pragma unroll
        for (int nt = 0; nt < 4; nt++)
            #pragma unroll
            for (int q = 0; q < 4; q++) acc[mt][nt][q] = 0.0f;

    const int arow = tid >> 1;
    const int acol = (tid & 1) * 16;
    const int frow = lane >> 2;
    const int fcol = 2 * (lane & 3);

    for (int kc = 0; kc < 128; kc += 32) {
        uint4 v0 = make_uint4(0, 0, 0, 0), v1 = make_uint4(0, 0, 0, 0);
        int gr = row0 + arow;
        if (gr < M) {
            const uint4* s = (const uint4*)&A[(size_t)gr * 128 + kc + acol];
            v0 = s[0]; v1 = s[1];
        }
        __syncthreads();
        *(uint4*)&As[arow * AS_STRIDE + acol]     = v0;
        *(uint4*)&As[arow * AS_STRIDE + acol + 8] = v1;
        __syncthreads();

        #pragma unroll
        for (int kk = 0; kk < 32; kk += 16) {
            unsigned int a[2][4];
            #pragma unroll
            for (int mt = 0; mt < 2; mt++) {
                int r = wm + mt * 16 + frow;
                int c = kk + fcol;
                a[mt][0] = *(const unsigned int*)&As[r * AS_STRIDE + c];
                a[mt][1] = *(const unsigned int*)&As[(r + 8) * AS_STRIDE + c];
                a[mt][2] = *(const unsigned int*)&As[r * AS_STRIDE + c + 8];
                a[mt][3] = *(const unsigned int*)&As[(r + 8) * AS_STRIDE + c + 8];
            }
            #pragma unroll
            for (int nt = 0; nt < 4; nt++) {
                int n = wn + nt * 8 + frow;
                int ck = kc + kk + fcol;
                unsigned int b0 = *(const unsigned int*)&Bs[n * BS_STRIDE + ck];
                unsigned int b1 = *(const unsigned int*)&Bs[n * BS_STRIDE + ck + 8];
                mma16816(acc[0][nt], a[0], b0, b1);
                mma16816(acc[1][nt], a[1], b0, b1);
            }
        }
    }

    #pragma unroll
    for (int mt = 0; mt < 2; mt++) {
        int r = row0 + wm + mt * 16 + frow;
        #pragma unroll
        for (int nt = 0; nt < 4; nt++) {
            int c = col0 + wn + nt * 8 + fcol;
            float2 bb = *(const float2*)&bias[c];
            if (r < M) {
                float2 v = make_float2(acc[mt][nt][0] + bb.x, acc[mt][nt][1] + bb.y);
                *(float2*)&C[(size_t)r * Ncols + c] = v;
            }
            if (r + 8 < M) {
                float2 v = make_float2(acc[mt][nt][2] + bb.x, acc[mt][nt][3] + bb.y);
                *(float2*)&C[(size_t)(r + 8) * Ncols + c] = v;
            }
        }
    }
}

// ---------------------------------------------------------------------------
// node_alpha1: warp per node (exact R6).
// ---------------------------------------------------------------------------
__global__ __launch_bounds__(256)
void node_alpha1(const __half* __restrict__ h,
                 const float* __restrict__ a_src,
                 const float* __restrict__ a_dst,
                 float* __restrict__ al_s,
                 float* __restrict__ al_d, int N) {
    int w = (blockIdx.x * blockDim.x + threadIdx.x) >> 5;
    int lane = threadIdx.x & 31;
    if (w >= N) return;
    uint2 raw = *(const uint2*)&h[(size_t)w * 128 + lane * 4];
    float2 f0 = __half22float2(*(const __half2*)&raw.x);
    float2 f1 = __half22float2(*(const __half2*)&raw.y);
    float4 asv = *(const float4*)&a_src[lane * 4];
    float4 adv = *(const float4*)&a_dst[lane * 4];
    float ps = f0.x * asv.x + f0.y * asv.y + f1.x * asv.z + f1.y * asv.w;
    float pd = f0.x * adv.x + f0.y * adv.y + f1.x * adv.z + f1.y * adv.w;
    #pragma unroll
    for (int off = 4; off > 0; off >>= 1) {
        ps += __shfl_xor_sync(0xFFFFFFFFu, ps, off);
        pd += __shfl_xor_sync(0xFFFFFFFFu, pd, off);
    }
    if ((lane & 7) == 0) {
        int hd = lane >> 3;
        al_s[w * 4 + hd] = ps;
        al_d[w * 4 + hd] = pd;
    }
}

// als2 from agg1h (128-dim dot with folded wa2 vectors)
__global__ __launch_bounds__(256)
void als2_k(const __half* __restrict__ h,
            const float* __restrict__ wa2s, const float* __restrict__ wa2d,
            float* __restrict__ als, float* __restrict__ ald, int N) {
    int w = (blockIdx.x * blockDim.x + threadIdx.x) >> 5;
    int lane = threadIdx.x & 31;
    if (w >= N) return;
    uint2 raw = *(const uint2*)&h[(size_t)w * 128 + lane * 4];
    float2 f0 = __half22float2(*(const __half2*)&raw.x);
    float2 f1 = __half22float2(*(const __half2*)&raw.y);
    float4 s = *(const float4*)&wa2s[lane * 4];
    float4 d = *(const float4*)&wa2d[lane * 4];
    float ps = f0.x * s.x + f0.y * s.y + f1.x * s.z + f1.y * s.w;
    float pd = f0.x * d.x + f0.y * d.y + f1.x * d.z + f1.y * d.w;
    #pragma unroll
    for (int off = 16; off > 0; off >>= 1) {
        ps += __shfl_xor_sync(0xFFFFFFFFu, ps, off);
        pd += __shfl_xor_sync(0xFFFFFFFFu, pd, off);
    }
    if (lane == 0) { als[w] = ps; ald[w] = pd; }
}

// ---------------------------------------------------------------------------
// Layer-1 fused gather, MLP=4 (exact R6). fp16 out + bias + relu.
// ---------------------------------------------------------------------------
__global__ __launch_bounds__(256)
void gather_agg1(const int* __restrict__ rowstart, const int* __restrict__ ssrc,
                 const float* __restrict__ als, const float* __restrict__ ald,
                 const __half* __restrict__ hlin, const float* __restrict__ bias,
                 __half* __restrict__ outp, int N) {
    int w = (blockIdx.x * blockDim.x + threadIdx.x) >> 5;
    int lane = threadIdx.x & 31;
    if (w >= N) return;
    const int beg = rowstart[w];
    const int end = rowstart[w + 1];
    const int head = lane >> 3;
    const float ad_h = ald[w * 4 + head];

    float ssum = 0.f;
    float4 acc = make_float4(0.f, 0.f, 0.f, 0.f);

    int j = beg;
    for (; j + 4 <= end; j += 4) {
        int sn0 = ssrc[j], sn1 = ssrc[j + 1], sn2 = ssrc[j + 2], sn3 = ssrc[j + 3];
        float al0 = als[sn0 * 4 + head];
        float al1 = als[sn1 * 4 + head];
        float al2 = als[sn2 * 4 + head];
        float al3 = als[sn3 * 4 + head];
        uint2 r0 = *(const uint2*)&hlin[(size_t)sn0 * 128 + lane * 4];
        uint2 r1 = *(const uint2*)&hlin[(size_t)sn1 * 128 + lane * 4];
        uint2 r2 = *(const uint2*)&hlin[(size_t)sn2 * 128 + lane * 4];
        uint2 r3 = *(const uint2*)&hlin[(size_t)sn3 * 128 + lane * 4];
        float e0 = __expf(lrelu(al0 + ad_h));
        float e1 = __expf(lrelu(al1 + ad_h));
        float e2 = __expf(lrelu(al2 + ad_h));
        float e3 = __expf(lrelu(al3 + ad_h));
        ssum += (e0 + e1) + (e2 + e3);
        float2 a, b;
        a = __half22float2(*(const __half2*)&r0.x);
        b = __half22float2(*(const __half2*)&r0.y);
        acc.x = fmaf(e0, a.x, acc.x); acc.y = fmaf(e0, a.y, acc.y);
        acc.z = fmaf(e0, b.x, acc.z); acc.w = fmaf(e0, b.y, acc.w);
        a = __half22float2(*(const __half2*)&r1.x);
        b = __half22float2(*(const __half2*)&r1.y);
        acc.x = fmaf(e1, a.x, acc.x); acc.y = fmaf(e1, a.y, acc.y);
        acc.z = fmaf(e1, b.x, acc.z); acc.w = fmaf(e1, b.y, acc.w);
        a = __half22float2(*(const __half2*)&r2.x);
        b = __half22float2(*(const __half2*)&r2.y);
        acc.x = fmaf(e2, a.x, acc.x); acc.y = fmaf(e2, a.y, acc.y);
        acc.z = fmaf(e2, b.x, acc.z); acc.w = fmaf(e2, b.y, acc.w);
        a = __half22float2(*(const __half2*)&r3.x);
        b = __half22float2(*(const __half2*)&r3.y);
        acc.x = fmaf(e3, a.x, acc.x); acc.y = fmaf(e3, a.y, acc.y);
        acc.z = fmaf(e3, b.x, acc.z); acc.w = fmaf(e3, b.y, acc.w);
    }
    for (; j < end; j++) {
        int sn = ssrc[j];
        float e = __expf(lrelu(als[sn * 4 + head] + ad_h));
        uint2 r = *(const uint2*)&hlin[(size_t)sn * 128 + lane * 4];
        ssum += e;
        float2 a = __half22float2(*(const __half2*)&r.x);
        float2 b = __half22float2(*(const __half2*)&r.y);
        acc.x = fmaf(e, a.x, acc.x); acc.y = fmaf(e, a.y, acc.y);
        acc.z = fmaf(e, b.x, acc.z); acc.w = fmaf(e, b.y, acc.w);
    }
    const float inv = 1.0f / (ssum + 1e-16f);
    float4 bb = *(const float4*)&bias[lane * 4];
    acc.x = fmaxf(fmaf(acc.x, inv, bb.x), 0.f);
    acc.y = fmaxf(fmaf(acc.y, inv, bb.y), 0.f);
    acc.z = fmaxf(fmaf(acc.z, inv, bb.z), 0.f);
    acc.w = fmaxf(fmaf(acc.w, inv, bb.w), 0.f);
    __half2 h0 = __floats2half2_rn(acc.x, acc.y);
    __half2 h1 = __floats2half2_rn(acc.z, acc.w);
    uint2 u;
    u.x = *(unsigned int*)&h0;
    u.y = *(unsigned int*)&h1;
    *(uint2*)&outp[(size_t)w * 128 + lane * 4] = u;
}

// ---------------------------------------------------------------------------
// Layer-2 gather of agg1 rows (128-dim, single alpha). MLP=4. fp16 out.
// ---------------------------------------------------------------------------
__global__ __launch_bounds__(256)
void gather_h1(const int* __restrict__ rowstart, const int* __restrict__ ssrc,
               const float* __restrict__ als, const float* __restrict__ ald,
               const __half* __restrict__ h1, __half* __restrict__ outp, int N) {
    int w = (blockIdx.x * blockDim.x + threadIdx.x) >> 5;
    int lane = threadIdx.x & 31;
    if (w >= N) return;
    const int beg = rowstart[w];
    const int end = rowstart[w + 1];
    const float ad = ald[w];

    float ssum = 0.f;
    float4 acc = make_float4(0.f, 0.f, 0.f, 0.f);

    int j = beg;
    for (; j + 4 <= end; j += 4) {
        int sn0 = ssrc[j], sn1 = ssrc[j + 1], sn2 = ssrc[j + 2], sn3 = ssrc[j + 3];
        float al0 = als[sn0], al1 = als[sn1], al2 = als[sn2], al3 = als[sn3];
        uint2 r0 = *(const uint2*)&h1[(size_t)sn0 * 128 + lane * 4];
        uint2 r1 = *(const uint2*)&h1[(size_t)sn1 * 128 + lane * 4];
        uint2 r2 = *(const uint2*)&h1[(size_t)sn2 * 128 + lane * 4];
        uint2 r3 = *(const uint2*)&h1[(size_t)sn3 * 128 + lane * 4];
        float e0 = __expf(lrelu(al0 + ad));
        float e1 = __expf(lrelu(al1 + ad));
        float e2 = __expf(lrelu(al2 + ad));
        float e3 = __expf(lrelu(al3 + ad));
        ssum += (e0 + e1) + (e2 + e3);
        float2 a, b;
        a = __half22float2(*(const __half2*)&r0.x);
        b = __half22float2(*(const __half2*)&r0.y);
        acc.x = fmaf(e0, a.x, acc.x); acc.y = fmaf(e0, a.y, acc.y);
        acc.z = fmaf(e0, b.x, acc.z); acc.w = fmaf(e0, b.y, acc.w);
        a = __half22float2(*(const __half2*)&r1.x);
        b = __half22float2(*(const __half2*)&r1.y);
        acc.x = fmaf(e1, a.x, acc.x); acc.y = fmaf(e1, a.y, acc.y);
        acc.z = fmaf(e1, b.x, acc.z); acc.w = fmaf(e1, b.y, acc.w);
        a = __half22float2(*(const __half2*)&r2.x);
        b = __half22float2(*(const __half2*)&r2.y);
        acc.x = fmaf(e2, a.x, acc.x); acc.y = fmaf(e2, a.y, acc.y);
        acc.z = fmaf(e2, b.x, acc.z); acc.w = fmaf(e2, b.y, acc.w);
        a = __half22float2(*(const __half2*)&r3.x);
        b = __half22float2(*(const __half2*)&r3.y);
        acc.x = fmaf(e3, a.x, acc.x); acc.y = fmaf(e3, a.y, acc.y);
        acc.z = fmaf(e3, b.x, acc.z); acc.w = fmaf(e3, b.y, acc.w);
    }
    for (; j < end; j++) {
        int sn = ssrc[j];
        float e = __expf(lrelu(als[sn] + ad));
        uint2 r = *(const uint2*)&h1[(size_t)sn * 128 + lane * 4];
        ssum += e;
        float2 a = __half22float2(*(const __half2*)&r.x);
        float2 b = __half22float2(*(const __half2*)&r.y);
        acc.x = fmaf(e, a.x, acc.x); acc.y = fmaf(e, a.y, acc.y);
        acc.z = fmaf(e, b.x, acc.z); acc.w = fmaf(e, b.y, acc.w);
    }
    const float inv = 1.0f / (ssum + 1e-16f);
    __half2 h0 = __floats2half2_rn(acc.x * inv, acc.y * inv);
    __half2 h1o = __floats2half2_rn(acc.z * inv, acc.w * inv);
    uint2 u;
    u.x = *(unsigned int*)&h0;
    u.y = *(unsigned int*)&h1o;
    *(uint2*)&outp[(size_t)w * 128 + lane * 4] = u;
}

// ---------------------------------------------------------------------------
// Launch
// ---------------------------------------------------------------------------
extern "C" void kernel_launch(void* const* d_in, const int* in_sizes, int n_in,
                              void* d_out, int out_size) {
    const float* x   = (const float*)d_in[0];
    const int*   ei  = (const int*)d_in[1];
    const float* W1  = (const float*)d_in[2];
    const float* as1 = (const float*)d_in[3];
    const float* ad1 = (const float*)d_in[4];
    const float* b1  = (const float*)d_in[5];
    const float* W2  = (const float*)d_in[6];
    const float* as2 = (const float*)d_in[7];
    const float* ad2 = (const float*)d_in[8];
    const float* b2  = (const float*)d_in[9];
    float* out = (float*)d_out;

    const int N = in_sizes[0] / 128;   // 50000
    const int E = in_sizes[1] / 2;     // 1600000

    float *wa2s, *wa2d, *als1p, *ald1p, *als2p, *ald2p;
    __half *xh, *wt1h, *wt2h, *hlin1, *agg1h, *agghx;
    int *cntp, *rowp, *curp, *ssrcp;
    cudaGetSymbolAddress((void**)&xh,    g_xh);
    cudaGetSymbolAddress((void**)&wt1h,  g_wt1h);
    cudaGetSymbolAddress((void**)&wt2h,  g_wt2h);
    cudaGetSymbolAddress((void**)&wa2s,  g_wa2s);
    cudaGetSymbolAddress((void**)&wa2d,  g_wa2d);
    cudaGetSymbolAddress((void**)&hlin1, g_hlin1);
    cudaGetSymbolAddress((void**)&als1p, g_als1);
    cudaGetSymbolAddress((void**)&ald1p, g_ald1);
    cudaGetSymbolAddress((void**)&agg1h, g_agg1h);
    cudaGetSymbolAddress((void**)&als2p, g_als2);
    cudaGetSymbolAddress((void**)&ald2p, g_ald2);
    cudaGetSymbolAddress((void**)&agghx, g_agghx);
    cudaGetSymbolAddress((void**)&cntp,  g_count);
    cudaGetSymbolAddress((void**)&rowp,  g_rowstart);
    cudaGetSymbolAddress((void**)&curp,  g_cursor);
    cudaGetSymbolAddress((void**)&ssrcp, g_sorted_src);

    static cudaStream_t s2 = nullptr;
    static cudaEvent_t ev_fork = nullptr, ev_csr = nullptr;
    if (s2 == nullptr) {
        cudaStreamCreateWithFlags(&s2, cudaStreamNonBlocking);
        cudaEventCreateWithFlags(&ev_fork, cudaEventDisableTiming);
        cudaEventCreateWithFlags(&ev_csr,  cudaEventDisableTiming);
    }

    const int NW_BLOCKS = (N * 32 + 255) / 256;
    const int HIST_THREADS = (E >> 2) + (E & 3);
    const int SCAT_THREADS = (E >> 2) + N + (E & 3);

    // --- fork: CSR build on s2 ---
    cudaEventRecord(ev_fork, 0);
    cudaStreamWaitEvent(s2, ev_fork, 0);
    cudaMemsetAsync(cntp, 0, (size_t)N * sizeof(int), s2);
    hist_dst_v<<<(HIST_THREADS + 255) / 256, 256, 0, s2>>>(ei, E, cntp);
    scan_counts<<<1, 1024, 0, s2>>>(cntp, rowp, curp, N);
    scatter_edges_v<<<(SCAT_THREADS + 255) / 256, 256, 0, s2>>>(ei, E, N, curp, ssrcp);
    cudaEventRecord(ev_csr, s2);

    // --- main: conversions + GEMM1 + alpha1 (exact R6 layer 1) ---
    cvt_f2h<<<(N * 128 / 4 + 255) / 256, 256>>>(x, xh, N * 128 / 4);
    cvt_wts<<<(128 * 128 + 256 * 128 + 255) / 256, 256>>>(W1, wt1h, W2, wt2h);
    cvt_wa2<<<1, 128>>>(W2, as2, ad2, wa2s, wa2d);
    {
        dim3 grid((N + 127) / 128, 2);
        hgemm_k128<<<grid, 256>>>(xh, wt1h, hlin1, N, 128);
    }
    node_alpha1<<<NW_BLOCKS, 256>>>(hlin1, as1, ad1, als1p, ald1p, N);

    // --- join CSR; gather1 -> agg1h (fp16, bias+relu fused) ---
    cudaStreamWaitEvent(0, ev_csr, 0);
    gather_agg1<<<NW_BLOCKS, 256>>>(rowp, ssrcp, als1p, ald1p, hlin1, b1, agg1h, N);

    // --- layer 2: als2 (folded) -> 128-dim gather -> GEMM2 (+bias) -> out ---
    als2_k<<<NW_BLOCKS, 256>>>(agg1h, wa2s, wa2d, als2p, ald2p, N);
    gather_h1<<<NW_BLOCKS, 256>>>(rowp, ssrcp, als2p, ald2p, agg1h, agghx, N);
    {
        dim3 grid((N + 127) / 128, 4);
        hgemm_f32out<<<grid, 256>>>(agghx, wt2h, b2, out, N, 256);
    }
}

// round 16
// speedup vs baseline: 1.3876x; 1.0061x over previous
#include <cuda_runtime.h>
#include <cuda_fp16.h>

// ---------------------------------------------------------------------------
// GAT encoder, R15: LDG-instruction-diet gathers.
//   Per 4-edge batch: ssrc via one int4 load; als via one lane-parallel
//   coalesced load + single exp + shfl broadcast (was 4 LDG + 4 MUFU).
//   Layer 2 stays aggregate-before-GEMM (128-dim gather). CSR on s2.
// ---------------------------------------------------------------------------

#define NNODES 50000
#define EMAX   1700000

__device__ __align__(16) __half g_xh[NNODES * 128];
__device__ __align__(16) __half g_wt1h[128 * 128];
__device__ __align__(16) __half g_wt2h[256 * 128];
__device__ __align__(16) float  g_wa2s[128];
__device__ __align__(16) float  g_wa2d[128];
__device__ __align__(16) __half g_hlin1[NNODES * 128];
__device__ __align__(16) float  g_als1[NNODES * 4];
__device__ __align__(16) float  g_ald1[NNODES * 4];
__device__ __align__(16) __half g_agg1h[NNODES * 128];
__device__ __align__(16) float  g_als2[NNODES];
__device__ __align__(16) float  g_ald2[NNODES];
__device__ __align__(16) __half g_agghx[NNODES * 128];
__device__ int g_count[NNODES];
__device__ int g_rowstart[NNODES + 1];
__device__ int g_cursor[NNODES];
__device__ int g_sorted_src[EMAX];

__device__ __forceinline__ float lrelu(float x) {
    return x > 0.0f ? x : 0.2f * x;
}

// ---------------------------------------------------------------------------
// Conversions
// ---------------------------------------------------------------------------
__global__ void cvt_f2h(const float* __restrict__ in, __half* __restrict__ out, int n4) {
    int i = blockIdx.x * blockDim.x + threadIdx.x;
    if (i >= n4) return;
    float4 v = *(const float4*)&in[i * 4];
    __half2 h0 = __floats2half2_rn(v.x, v.y);
    __half2 h1 = __floats2half2_rn(v.z, v.w);
    uint2 u;
    u.x = *(unsigned int*)&h0;
    u.y = *(unsigned int*)&h1;
    *(uint2*)&out[i * 4] = u;
}

__global__ void cvt_wts(const float* __restrict__ W1, __half* __restrict__ WT1,
                        const float* __restrict__ W2, __half* __restrict__ WT2) {
    int i = blockIdx.x * blockDim.x + threadIdx.x;
    if (i < 128 * 128) {
        int n = i >> 7, k = i & 127;
        WT1[i] = __float2half(W1[k * 128 + n]);
    } else if (i < 128 * 128 + 256 * 128) {
        int j = i - 128 * 128;
        int n = j >> 7, k = j & 127;
        WT2[j] = __float2half(W2[k * 256 + n]);
    }
}

__global__ __launch_bounds__(128, 1)
void cvt_wa2(const float* __restrict__ W2,
             const float* __restrict__ as2, const float* __restrict__ ad2,
             float* __restrict__ wa2s, float* __restrict__ wa2d) {
    int k = threadIdx.x;
    float s = 0.f, d = 0.f;
    #pragma unroll 8
    for (int c = 0; c < 256; c++) {
        float w = W2[k * 256 + c];
        s = fmaf(w, as2[c], s);
        d = fmaf(w, ad2[c], d);
    }
    wa2s[k] = s;
    wa2d[k] = d;
}

// ---------------------------------------------------------------------------
// CSR build (vectorized; self-loops folded into scan).
// ---------------------------------------------------------------------------
__global__ void hist_dst_v(const int* __restrict__ ei, int E,
                           int* __restrict__ cnt) {
    int i = blockIdx.x * blockDim.x + threadIdx.x;
    int nv = E >> 2;
    if (i < nv) {
        int4 d4 = *(const int4*)&ei[E + i * 4];
        atomicAdd(&cnt[d4.x], 1);
        atomicAdd(&cnt[d4.y], 1);
        atomicAdd(&cnt[d4.z], 1);
        atomicAdd(&cnt[d4.w], 1);
    } else {
        int e = nv * 4 + (i - nv);
        if (e < E) atomicAdd(&cnt[ei[E + e]], 1);
    }
}

__global__ __launch_bounds__(1024, 1)
void scan_counts(const int* __restrict__ cnt, int* __restrict__ rowstart,
                 int* __restrict__ cursor, int N) {
    __shared__ int wsum[32];
    __shared__ int s_carry;
    const int tid = threadIdx.x, lane = tid & 31, wid = tid >> 5;
    if (tid == 0) s_carry = 0;
    __syncthreads();
    for (int base = 0; base < N; base += 4096) {
        int idx = base + tid * 4;
        int4 v = make_int4(-1, -1, -1, -1);
        if (idx + 3 < N) v = *(const int4*)&cnt[idx];
        else {
            if (idx + 0 < N) v.x = cnt[idx + 0];
            if (idx + 1 < N) v.y = cnt[idx + 1];
            if (idx + 2 < N) v.z = cnt[idx + 2];
            if (idx + 3 < N) v.w = cnt[idx + 3];
        }
        v.x += 1; v.y += 1; v.z += 1; v.w += 1;
        int tsum = v.x + v.y + v.z + v.w;
        int x = tsum;
        #pragma unroll
        for (int off = 1; off < 32; off <<= 1) {
            int y = __shfl_up_sync(0xFFFFFFFFu, x, off);
            if (lane >= off) x += y;
        }
        if (lane == 31) wsum[wid] = x;
        __syncthreads();
        if (wid == 0) {
            int w = wsum[lane];
            #pragma unroll
            for (int off = 1; off < 32; off <<= 1) {
                int y = __shfl_up_sync(0xFFFFFFFFu, w, off);
                if (lane >= off) w += y;
            }
            wsum[lane] = w;
        }
        __syncthreads();
        int carry = s_carry;
        int excl = carry + (wid > 0 ? wsum[wid - 1] : 0) + x - tsum;
        int e0 = excl, e1 = e0 + v.x, e2 = e1 + v.y, e3 = e2 + v.z;
        if (idx + 3 < N) {
            *(int4*)&rowstart[idx] = make_int4(e0, e1, e2, e3);
            *(int4*)&cursor[idx]   = make_int4(e0, e1, e2, e3);
        } else {
            if (idx + 0 < N) { rowstart[idx + 0] = e0; cursor[idx + 0] = e0; }
            if (idx + 1 < N) { rowstart[idx + 1] = e1; cursor[idx + 1] = e1; }
            if (idx + 2 < N) { rowstart[idx + 2] = e2; cursor[idx + 2] = e2; }
            if (idx + 3 < N) { rowstart[idx + 3] = e3; cursor[idx + 3] = e3; }
        }
        __syncthreads();
        if (tid == 1023) s_carry = carry + wsum[31];
        __syncthreads();
    }
    if (tid == 0) rowstart[N] = s_carry;
}

__global__ void scatter_edges_v(const int* __restrict__ ei, int E, int N,
                                int* __restrict__ cursor,
                                int* __restrict__ sorted_src) {
    int i = blockIdx.x * blockDim.x + threadIdx.x;
    int nv = E >> 2;
    if (i < nv) {
        int4 s4 = *(const int4*)&ei[i * 4];
        int4 d4 = *(const int4*)&ei[E + i * 4];
        int p0 = atomicAdd(&cursor[d4.x], 1);
        int p1 = atomicAdd(&cursor[d4.y], 1);
        int p2 = atomicAdd(&cursor[d4.z], 1);
        int p3 = atomicAdd(&cursor[d4.w], 1);
        sorted_src[p0] = s4.x;
        sorted_src[p1] = s4.y;
        sorted_src[p2] = s4.z;
        sorted_src[p3] = s4.w;
    } else if (i < nv + N) {
        int d = i - nv;
        int p = atomicAdd(&cursor[d], 1);
        sorted_src[p] = d;
    } else {
        int e = nv * 4 + (i - nv - N);
        if (e < E) {
            int s = ei[e], d = ei[E + e];
            int p = atomicAdd(&cursor[d], 1);
            sorted_src[p] = s;
        }
    }
}

// ---------------------------------------------------------------------------
// HGEMM (fp16 C): layer-1 GEMM.
// ---------------------------------------------------------------------------
#define AS_STRIDE 40
#define BS_STRIDE 136

__device__ __forceinline__ void mma16816(float* c, const unsigned int* a,
                                         unsigned int b0, unsigned int b1) {
    asm volatile(
        "mma.sync.aligned.m16n8k16.row.col.f32.f16.f16.f32 "
        "{%0,%1,%2,%3}, {%4,%5,%6,%7}, {%8,%9}, {%0,%1,%2,%3};"
        : "+f"(c[0]), "+f"(c[1]), "+f"(c[2]), "+f"(c[3])
        : "r"(a[0]), "r"(a[1]), "r"(a[2]), "r"(a[3]), "r"(b0), "r"(b1));
}

__global__ __launch_bounds__(256, 1)
void hgemm_k128(const __half* __restrict__ A, const __half* __restrict__ WT,
                __half* __restrict__ C, int M, int Ncols) {
    __shared__ __half As[128 * AS_STRIDE];
    __shared__ __half Bs[64 * BS_STRIDE];

    const int tid  = threadIdx.x;
    const int lane = tid & 31;
    const int wid  = tid >> 5;
    const int row0 = blockIdx.x * 128;
    const int col0 = blockIdx.y * 64;
    const int wm = (wid & 3) * 32;
    const int wn = (wid >> 2) * 32;

    {
        int n = tid >> 2;
        int p = (tid & 3) * 32;
        const uint4* src = (const uint4*)&WT[(size_t)(col0 + n) * 128 + p];
        uint4* dst = (uint4*)&Bs[n * BS_STRIDE + p];
        dst[0] = src[0]; dst[1] = src[1]; dst[2] = src[2]; dst[3] = src[3];
    }

    float acc[2][4][4];
    #pragma unroll
    for (int mt = 0; mt < 2; mt++)
        #pragma unroll
        for (int nt = 0; nt < 4; nt++)
            #pragma unroll
            for (int q = 0; q < 4; q++) acc[mt][nt][q] = 0.0f;

    const int arow = tid >> 1;
    const int acol = (tid & 1) * 16;
    const int frow = lane >> 2;
    const int fcol = 2 * (lane & 3);

    for (int kc = 0; kc < 128; kc += 32) {
        uint4 v0 = make_uint4(0, 0, 0, 0), v1 = make_uint4(0, 0, 0, 0);
        int gr = row0 + arow;
        if (gr < M) {
            const uint4* s = (const uint4*)&A[(size_t)gr * 128 + kc + acol];
            v0 = s[0]; v1 = s[1];
        }
        __syncthreads();
        *(uint4*)&As[arow * AS_STRIDE + acol]     = v0;
        *(uint4*)&As[arow * AS_STRIDE + acol + 8] = v1;
        __syncthreads();

        #pragma unroll
        for (int kk = 0; kk < 32; kk += 16) {
            unsigned int a[2][4];
            #pragma unroll
            for (int mt = 0; mt < 2; mt++) {
                int r = wm + mt * 16 + frow;
                int c = kk + fcol;
                a[mt][0] = *(const unsigned int*)&As[r * AS_STRIDE + c];
                a[mt][1] = *(const unsigned int*)&As[(r + 8) * AS_STRIDE + c];
                a[mt][2] = *(const unsigned int*)&As[r * AS_STRIDE + c + 8];
                a[mt][3] = *(const unsigned int*)&As[(r + 8) * AS_STRIDE + c + 8];
            }
            #pragma unroll
            for (int nt = 0; nt < 4; nt++) {
                int n = wn + nt * 8 + frow;
                int ck = kc + kk + fcol;
                unsigned int b0 = *(const unsigned int*)&Bs[n * BS_STRIDE + ck];
                unsigned int b1 = *(const unsigned int*)&Bs[n * BS_STRIDE + ck + 8];
                mma16816(acc[0][nt], a[0], b0, b1);
                mma16816(acc[1][nt], a[1], b0, b1);
            }
        }
    }

    #pragma unroll
    for (int mt = 0; mt < 2; mt++) {
        int r = row0 + wm + mt * 16 + frow;
        #pragma unroll
        for (int nt = 0; nt < 4; nt++) {
            int c = col0 + wn + nt * 8 + fcol;
            if (r < M) {
                __half2 h = __floats2half2_rn(acc[mt][nt][0], acc[mt][nt][1]);
                *(__half2*)&C[(size_t)r * Ncols + c] = h;
            }
            if (r + 8 < M) {
                __half2 h = __floats2half2_rn(acc[mt][nt][2], acc[mt][nt][3]);
                *(__half2*)&C[(size_t)(r + 8) * Ncols + c] = h;
            }
        }
    }
}

// ---------------------------------------------------------------------------
// HGEMM (fp32 C + bias): layer-2 GEMM -> out.
// ---------------------------------------------------------------------------
__global__ __launch_bounds__(256, 1)
void hgemm_f32out(const __half* __restrict__ A, const __half* __restrict__ WT,
                  const float* __restrict__ bias, float* __restrict__ C,
                  int M, int Ncols) {
    __shared__ __half As[128 * AS_STRIDE];
    __shared__ __half Bs[64 * BS_STRIDE];

    const int tid  = threadIdx.x;
    const int lane = tid & 31;
    const int wid  = tid >> 5;
    const int row0 = blockIdx.x * 128;
    const int col0 = blockIdx.y * 64;
    const int wm = (wid & 3) * 32;
    const int wn = (wid >> 2) * 32;

    {
        int n = tid >> 2;
        int p = (tid & 3) * 32;
        const uint4* src = (const uint4*)&WT[(size_t)(col0 + n) * 128 + p];
        uint4* dst = (uint4*)&Bs[n * BS_STRIDE + p];
        dst[0] = src[0]; dst[1] = src[1]; dst[2] = src[2]; dst[3] = src[3];
    }

    float acc[2][4][4];
    #pragma unroll
    for (int mt = 0; mt < 2; mt++)
        #pragma unroll
        for (int nt = 0; nt < 4; nt++)
            #pragma unroll
            for (int q = 0; q < 4; q++) acc[mt][nt][q] = 0.0f;

    const int arow = tid >> 1;
    const int acol = (tid & 1) * 16;
    const int frow = lane >> 2;
    const int fcol = 2 * (lane & 3);

    for (int kc = 0; kc < 128; kc += 32) {
        uint4 v0 = make_uint4(0, 0, 0, 0), v1 = make_uint4(0, 0, 0, 0);
        int gr = row0 + arow;
        if (gr < M) {
            const uint4* s = (const uint4*)&A[(size_t)gr * 128 + kc + acol];
            v0 = s[0]; v1 = s[1];
        }
        __syncthreads();
        *(uint4*)&As[arow * AS_STRIDE + acol]     = v0;
        *(uint4*)&As[arow * AS_STRIDE + acol + 8] = v1;
        __syncthreads();

        #pragma unroll
        for (int kk = 0; kk < 32; kk += 16) {
            unsigned int a[2][4];
            #pragma unroll
            for (int mt = 0; mt < 2; mt++) {
                int r = wm + mt * 16 + frow;
                int c = kk + fcol;
                a[mt][0] = *(const unsigned int*)&As[r * AS_STRIDE + c];
                a[mt][1] = *(const unsigned int*)&As[(r + 8) * AS_STRIDE + c];
                a[mt][2] = *(const unsigned int*)&As[r * AS_STRIDE + c + 8];
                a[mt][3] = *(const unsigned int*)&As[(r + 8) * AS_STRIDE + c + 8];
            }
            #pragma unroll
            for (int nt = 0; nt < 4; nt++) {
                int n = wn + nt * 8 + frow;
                int ck = kc + kk + fcol;
                unsigned int b0 = *(const unsigned int*)&Bs[n * BS_STRIDE + ck];
                unsigned int b1 = *(const unsigned int*)&Bs[n * BS_STRIDE + ck + 8];
                mma16816(acc[0][nt], a[0], b0, b1);
                mma16816(acc[1][nt], a[1], b0, b1);
            }
        }
    }

    #pragma unroll
    for (int mt = 0; mt < 2; mt++) {
        int r = row0 + wm + mt * 16 + frow;
        #pragma unroll
        for (int nt = 0; nt < 4; nt++) {
            int c = col0 + wn + nt * 8 + fcol;
            float2 bb = *(const float2*)&bias[c];
            if (r < M) {
                float2 v = make_float2(acc[mt][nt][0] + bb.x, acc[mt][nt][1] + bb.y);
                *(float2*)&C[(size_t)r * Ncols + c] = v;
            }
            if (r + 8 < M) {
                float2 v = make_float2(acc[mt][nt][2] + bb.x, acc[mt][nt][3] + bb.y);
                *(float2*)&C[(size_t)(r + 8) * Ncols + c] = v;
            }
        }
    }
}

// ---------------------------------------------------------------------------
// node_alpha1 + als2
// ---------------------------------------------------------------------------
__global__ __launch_bounds__(256)
void node_alpha1(const __half* __restrict__ h,
                 const float* __restrict__ a_src,
                 const float* __restrict__ a_dst,
                 float* __restrict__ al_s,
                 float* __restrict__ al_d, int N) {
    int w = (blockIdx.x * blockDim.x + threadIdx.x) >> 5;
    int lane = threadIdx.x & 31;
    if (w >= N) return;
    uint2 raw = *(const uint2*)&h[(size_t)w * 128 + lane * 4];
    float2 f0 = __half22float2(*(const __half2*)&raw.x);
    float2 f1 = __half22float2(*(const __half2*)&raw.y);
    float4 asv = *(const float4*)&a_src[lane * 4];
    float4 adv = *(const float4*)&a_dst[lane * 4];
    float ps = f0.x * asv.x + f0.y * asv.y + f1.x * asv.z + f1.y * asv.w;
    float pd = f0.x * adv.x + f0.y * adv.y + f1.x * adv.z + f1.y * adv.w;
    #pragma unroll
    for (int off = 4; off > 0; off >>= 1) {
        ps += __shfl_xor_sync(0xFFFFFFFFu, ps, off);
        pd += __shfl_xor_sync(0xFFFFFFFFu, pd, off);
    }
    if ((lane & 7) == 0) {
        int hd = lane >> 3;
        al_s[w * 4 + hd] = ps;
        al_d[w * 4 + hd] = pd;
    }
}

__global__ __launch_bounds__(256)
void als2_k(const __half* __restrict__ h,
            const float* __restrict__ wa2s, const float* __restrict__ wa2d,
            float* __restrict__ als, float* __restrict__ ald, int N) {
    int w = (blockIdx.x * blockDim.x + threadIdx.x) >> 5;
    int lane = threadIdx.x & 31;
    if (w >= N) return;
    uint2 raw = *(const uint2*)&h[(size_t)w * 128 + lane * 4];
    float2 f0 = __half22float2(*(const __half2*)&raw.x);
    float2 f1 = __half22float2(*(const __half2*)&raw.y);
    float4 s = *(const float4*)&wa2s[lane * 4];
    float4 d = *(const float4*)&wa2d[lane * 4];
    float ps = f0.x * s.x + f0.y * s.y + f1.x * s.z + f1.y * s.w;
    float pd = f0.x * d.x + f0.y * d.y + f1.x * d.z + f1.y * d.w;
    #pragma unroll
    for (int off = 16; off > 0; off >>= 1) {
        ps += __shfl_xor_sync(0xFFFFFFFFu, ps, off);
        pd += __shfl_xor_sync(0xFFFFFFFFu, pd, off);
    }
    if (lane == 0) { als[w] = ps; ald[w] = pd; }
}

// ---------------------------------------------------------------------------
// Layer-1 gather: int4 ssrc, lane-parallel als + single exp + shfl bcast.
// Per 4-edge batch: 6 LDG + 1 exp (was 12 LDG + 4 exp). fp16 out, bias+relu.
// ---------------------------------------------------------------------------
__global__ __launch_bounds__(256)
void gather_agg1(const int* __restrict__ rowstart, const int* __restrict__ ssrc,
                 const float* __restrict__ als, const float* __restrict__ ald,
                 const __half* __restrict__ hlin, const float* __restrict__ bias,
                 __half* __restrict__ outp, int N) {
    int w = (blockIdx.x * blockDim.x + threadIdx.x) >> 5;
    int lane = threadIdx.x & 31;
    if (w >= N) return;
    const int beg = rowstart[w];
    const int end = rowstart[w + 1];
    const int head = lane >> 3;
    const int q    = lane & 3;
    const int hsel = lane & 24;       // head << 3
    const float ad_h = ald[w * 4 + head];

    float ssum = 0.f;
    float4 acc = make_float4(0.f, 0.f, 0.f, 0.f);

    #define SCALAR_EDGE1(J)                                                    \
    {                                                                          \
        int sn = ssrc[J];                                                      \
        float e = __expf(lrelu(als[sn * 4 + head] + ad_h));                    \
        uint2 r = *(const uint2*)&hlin[(size_t)sn * 128 + lane * 4];           \
        ssum += e;                                                             \
        float2 a = __half22float2(*(const __half2*)&r.x);                      \
        float2 b = __half22float2(*(const __half2*)&r.y);                      \
        acc.x = fmaf(e, a.x, acc.x); acc.y = fmaf(e, a.y, acc.y);              \
        acc.z = fmaf(e, b.x, acc.z); acc.w = fmaf(e, b.y, acc.w);              \
    }

    int j = beg;
    int pro = (beg + 3) & ~3;
    if (pro > end) pro = end;
    for (; j < pro; j++) SCALAR_EDGE1(j)

    for (; j + 4 <= end; j += 4) {
        int4 sn4 = *(const int4*)&ssrc[j];
        int snq = (q == 0) ? sn4.x : (q == 1) ? sn4.y : (q == 2) ? sn4.z : sn4.w;
        float alv = als[snq * 4 + head];              // 1 coalesced LDG
        float ev = __expf(lrelu(alv + ad_h));         // 1 exp per batch
        float e0 = __shfl_sync(0xFFFFFFFFu, ev, hsel);
        float e1 = __shfl_sync(0xFFFFFFFFu, ev, hsel | 1);
        float e2 = __shfl_sync(0xFFFFFFFFu, ev, hsel | 2);
        float e3 = __shfl_sync(0xFFFFFFFFu, ev, hsel | 3);
        uint2 r0 = *(const uint2*)&hlin[(size_t)sn4.x * 128 + lane * 4];
        uint2 r1 = *(const uint2*)&hlin[(size_t)sn4.y * 128 + lane * 4];
        uint2 r2 = *(const uint2*)&hlin[(size_t)sn4.z * 128 + lane * 4];
        uint2 r3 = *(const uint2*)&hlin[(size_t)sn4.w * 128 + lane * 4];
        ssum += (e0 + e1) + (e2 + e3);
        float2 a, b;
        a = __half22float2(*(const __half2*)&r0.x);
        b = __half22float2(*(const __half2*)&r0.y);
        acc.x = fmaf(e0, a.x, acc.x); acc.y = fmaf(e0, a.y, acc.y);
        acc.z = fmaf(e0, b.x, acc.z); acc.w = fmaf(e0, b.y, acc.w);
        a = __half22float2(*(const __half2*)&r1.x);
        b = __half22float2(*(const __half2*)&r1.y);
        acc.x = fmaf(e1, a.x, acc.x); acc.y = fmaf(e1, a.y, acc.y);
        acc.z = fmaf(e1, b.x, acc.z); acc.w = fmaf(e1, b.y, acc.w);
        a = __half22float2(*(const __half2*)&r2.x);
        b = __half22float2(*(const __half2*)&r2.y);
        acc.x = fmaf(e2, a.x, acc.x); acc.y = fmaf(e2, a.y, acc.y);
        acc.z = fmaf(e2, b.x, acc.z); acc.w = fmaf(e2, b.y, acc.w);
        a = __half22float2(*(const __half2*)&r3.x);
        b = __half22float2(*(const __half2*)&r3.y);
        acc.x = fmaf(e3, a.x, acc.x); acc.y = fmaf(e3, a.y, acc.y);
        acc.z = fmaf(e3, b.x, acc.z); acc.w = fmaf(e3, b.y, acc.w);
    }
    for (; j < end; j++) SCALAR_EDGE1(j)
    #undef SCALAR_EDGE1

    const float inv = 1.0f / (ssum + 1e-16f);
    float4 bb = *(const float4*)&bias[lane * 4];
    acc.x = fmaxf(fmaf(acc.x, inv, bb.x), 0.f);
    acc.y = fmaxf(fmaf(acc.y, inv, bb.y), 0.f);
    acc.z = fmaxf(fmaf(acc.z, inv, bb.z), 0.f);
    acc.w = fmaxf(fmaf(acc.w, inv, bb.w), 0.f);
    __half2 h0 = __floats2half2_rn(acc.x, acc.y);
    __half2 h1 = __floats2half2_rn(acc.z, acc.w);
    uint2 u;
    u.x = *(unsigned int*)&h0;
    u.y = *(unsigned int*)&h1;
    *(uint2*)&outp[(size_t)w * 128 + lane * 4] = u;
}

// ---------------------------------------------------------------------------
// Layer-2 gather of agg1 rows: same LDG diet (single alpha per edge).
// ---------------------------------------------------------------------------
__global__ __launch_bounds__(256)
void gather_h1(const int* __restrict__ rowstart, const int* __restrict__ ssrc,
               const float* __restrict__ als, const float* __restrict__ ald,
               const __half* __restrict__ h1, __half* __restrict__ outp, int N) {
    int w = (blockIdx.x * blockDim.x + threadIdx.x) >> 5;
    int lane = threadIdx.x & 31;
    if (w >= N) return;
    const int beg = rowstart[w];
    const int end = rowstart[w + 1];
    const int q   = lane & 3;
    const float ad = ald[w];

    float ssum = 0.f;
    float4 acc = make_float4(0.f, 0.f, 0.f, 0.f);

    #define SCALAR_EDGE2(J)                                                    \
    {                                                                          \
        int sn = ssrc[J];                                                      \
        float e = __expf(lrelu(als[sn] + ad));                                 \
        uint2 r = *(const uint2*)&h1[(size_t)sn * 128 + lane * 4];             \
        ssum += e;                                                             \
        float2 a = __half22float2(*(const __half2*)&r.x);                      \
        float2 b = __half22float2(*(const __half2*)&r.y);                      \
        acc.x = fmaf(e, a.x, acc.x); acc.y = fmaf(e, a.y, acc.y);              \
        acc.z = fmaf(e, b.x, acc.z); acc.w = fmaf(e, b.y, acc.w);              \
    }

    int j = beg;
    int pro = (beg + 3) & ~3;
    if (pro > end) pro = end;
    for (; j < pro; j++) SCALAR_EDGE2(j)

    for (; j + 4 <= end; j += 4) {
        int4 sn4 = *(const int4*)&ssrc[j];
        int snq = (q == 0) ? sn4.x : (q == 1) ? sn4.y : (q == 2) ? sn4.z : sn4.w;
        float alv = als[snq];                          // 1 coalesced LDG
        float ev = __expf(lrelu(alv + ad));            // 1 exp per batch
        float e0 = __shfl_sync(0xFFFFFFFFu, ev, 0);
        float e1 = __shfl_sync(0xFFFFFFFFu, ev, 1);
        float e2 = __shfl_sync(0xFFFFFFFFu, ev, 2);
        float e3 = __shfl_sync(0xFFFFFFFFu, ev, 3);
        uint2 r0 = *(const uint2*)&h1[(size_t)sn4.x * 128 + lane * 4];
        uint2 r1 = *(const uint2*)&h1[(size_t)sn4.y * 128 + lane * 4];
        uint2 r2 = *(const uint2*)&h1[(size_t)sn4.z * 128 + lane * 4];
        uint2 r3 = *(const uint2*)&h1[(size_t)sn4.w * 128 + lane * 4];
        ssum += (e0 + e1) + (e2 + e3);
        float2 a, b;
        a = __half22float2(*(const __half2*)&r0.x);
        b = __half22float2(*(const __half2*)&r0.y);
        acc.x = fmaf(e0, a.x, acc.x); acc.y = fmaf(e0, a.y, acc.y);
        acc.z = fmaf(e0, b.x, acc.z); acc.w = fmaf(e0, b.y, acc.w);
        a = __half22float2(*(const __half2*)&r1.x);
        b = __half22float2(*(const __half2*)&r1.y);
        acc.x = fmaf(e1, a.x, acc.x); acc.y = fmaf(e1, a.y, acc.y);
        acc.z = fmaf(e1, b.x, acc.z); acc.w = fmaf(e1, b.y, acc.w);
        a = __half22float2(*(const __half2*)&r2.x);
        b = __half22float2(*(const __half2*)&r2.y);
        acc.x = fmaf(e2, a.x, acc.x); acc.y = fmaf(e2, a.y, acc.y);
        acc.z = fmaf(e2, b.x, acc.z); acc.w = fmaf(e2, b.y, acc.w);
        a = __half22float2(*(const __half2*)&r3.x);
        b = __half22float2(*(const __half2*)&r3.y);
        acc.x = fmaf(e3, a.x, acc.x); acc.y = fmaf(e3, a.y, acc.y);
        acc.z = fmaf(e3, b.x, acc.z); acc.w = fmaf(e3, b.y, acc.w);
    }
    for (; j < end; j++) SCALAR_EDGE2(j)
    #undef SCALAR_EDGE2

    const float inv = 1.0f / (ssum + 1e-16f);
    __half2 h0 = __floats2half2_rn(acc.x * inv, acc.y * inv);
    __half2 h1o = __floats2half2_rn(acc.z * inv, acc.w * inv);
    uint2 u;
    u.x = *(unsigned int*)&h0;
    u.y = *(unsigned int*)&h1o;
    *(uint2*)&outp[(size_t)w * 128 + lane * 4] = u;
}

// ---------------------------------------------------------------------------
// Launch
// ---------------------------------------------------------------------------
extern "C" void kernel_launch(void* const* d_in, const int* in_sizes, int n_in,
                              void* d_out, int out_size) {
    const float* x   = (const float*)d_in[0];
    const int*   ei  = (const int*)d_in[1];
    const float* W1  = (const float*)d_in[2];
    const float* as1 = (const float*)d_in[3];
    const float* ad1 = (const float*)d_in[4];
    const float* b1  = (const float*)d_in[5];
    const float* W2  = (const float*)d_in[6];
    const float* as2 = (const float*)d_in[7];
    const float* ad2 = (const float*)d_in[8];
    const float* b2  = (const float*)d_in[9];
    float* out = (float*)d_out;

    const int N = in_sizes[0] / 128;   // 50000
    const int E = in_sizes[1] / 2;     // 1600000

    float *wa2s, *wa2d, *als1p, *ald1p, *als2p, *ald2p;
    __half *xh, *wt1h, *wt2h, *hlin1, *agg1h, *agghx;
    int *cntp, *rowp, *curp, *ssrcp;
    cudaGetSymbolAddress((void**)&xh,    g_xh);
    cudaGetSymbolAddress((void**)&wt1h,  g_wt1h);
    cudaGetSymbolAddress((void**)&wt2h,  g_wt2h);
    cudaGetSymbolAddress((void**)&wa2s,  g_wa2s);
    cudaGetSymbolAddress((void**)&wa2d,  g_wa2d);
    cudaGetSymbolAddress((void**)&hlin1, g_hlin1);
    cudaGetSymbolAddress((void**)&als1p, g_als1);
    cudaGetSymbolAddress((void**)&ald1p, g_ald1);
    cudaGetSymbolAddress((void**)&agg1h, g_agg1h);
    cudaGetSymbolAddress((void**)&als2p, g_als2);
    cudaGetSymbolAddress((void**)&ald2p, g_ald2);
    cudaGetSymbolAddress((void**)&agghx, g_agghx);
    cudaGetSymbolAddress((void**)&cntp,  g_count);
    cudaGetSymbolAddress((void**)&rowp,  g_rowstart);
    cudaGetSymbolAddress((void**)&curp,  g_cursor);
    cudaGetSymbolAddress((void**)&ssrcp, g_sorted_src);

    static cudaStream_t s2 = nullptr;
    static cudaEvent_t ev_fork = nullptr, ev_csr = nullptr;
    if (s2 == nullptr) {
        cudaStreamCreateWithFlags(&s2, cudaStreamNonBlocking);
        cudaEventCreateWithFlags(&ev_fork, cudaEventDisableTiming);
        cudaEventCreateWithFlags(&ev_csr,  cudaEventDisableTiming);
    }

    const int NW_BLOCKS = (N * 32 + 255) / 256;
    const int HIST_THREADS = (E >> 2) + (E & 3);
    const int SCAT_THREADS = (E >> 2) + N + (E & 3);

    // --- fork: CSR build on s2 ---
    cudaEventRecord(ev_fork, 0);
    cudaStreamWaitEvent(s2, ev_fork, 0);
    cudaMemsetAsync(cntp, 0, (size_t)N * sizeof(int), s2);
    hist_dst_v<<<(HIST_THREADS + 255) / 256, 256, 0, s2>>>(ei, E, cntp);
    scan_counts<<<1, 1024, 0, s2>>>(cntp, rowp, curp, N);
    scatter_edges_v<<<(SCAT_THREADS + 255) / 256, 256, 0, s2>>>(ei, E, N, curp, ssrcp);
    cudaEventRecord(ev_csr, s2);

    // --- main: conversions + GEMM1 + alpha1 ---
    cvt_f2h<<<(N * 128 / 4 + 255) / 256, 256>>>(x, xh, N * 128 / 4);
    cvt_wts<<<(128 * 128 + 256 * 128 + 255) / 256, 256>>>(W1, wt1h, W2, wt2h);
    cvt_wa2<<<1, 128>>>(W2, as2, ad2, wa2s, wa2d);
    {
        dim3 grid((N + 127) / 128, 2);
        hgemm_k128<<<grid, 256>>>(xh, wt1h, hlin1, N, 128);
    }
    node_alpha1<<<NW_BLOCKS, 256>>>(hlin1, as1, ad1, als1p, ald1p, N);

    // --- join CSR; gather1 -> agg1h (fp16, bias+relu fused) ---
    cudaStreamWaitEvent(0, ev_csr, 0);
    gather_agg1<<<NW_BLOCKS, 256>>>(rowp, ssrcp, als1p, ald1p, hlin1, b1, agg1h, N);

    // --- layer 2: als2 (folded) -> 128-dim gather -> GEMM2 (+bias) -> out ---
    als2_k<<<NW_BLOCKS, 256>>>(agg1h, wa2s, wa2d, als2p, ald2p, N);
    gather_h1<<<NW_BLOCKS, 256>>>(rowp, ssrcp, als2p, ald2p, agg1h, agghx, N);
    {
        dim3 grid((N + 127) / 128, 4);
        hgemm_f32out<<<grid, 256>>>(agghx, wt2h, b2, out, N, 256);
    }
}

// round 17
// speedup vs baseline: 1.4168x; 1.0211x over previous
#include <cuda_runtime.h>
#include <cuda_fp16.h>

// ---------------------------------------------------------------------------
// GAT encoder, R16: fusion harvest.
//   - node_alpha1 fused into GEMM1 epilogue (per-warp head-exact col range).
//   - als2/ald2 fused into gather_agg1 epilogue (fp32 acc dot).
//   - cvt_wa2 merged into cvt_wts.
// Gathers / CSR / GEMM2 identical to 231.2us best.
// ---------------------------------------------------------------------------

#define NNODES 50000
#define EMAX   1700000

__device__ __align__(16) __half g_xh[NNODES * 128];
__device__ __align__(16) __half g_wt1h[128 * 128];
__device__ __align__(16) __half g_wt2h[256 * 128];
__device__ __align__(16) float  g_wa2s[128];
__device__ __align__(16) float  g_wa2d[128];
__device__ __align__(16) __half g_hlin1[NNODES * 128];
__device__ __align__(16) float  g_als1[NNODES * 4];
__device__ __align__(16) float  g_ald1[NNODES * 4];
__device__ __align__(16) __half g_agg1h[NNODES * 128];
__device__ __align__(16) float  g_als2[NNODES];
__device__ __align__(16) float  g_ald2[NNODES];
__device__ __align__(16) __half g_agghx[NNODES * 128];
__device__ int g_count[NNODES];
__device__ int g_rowstart[NNODES + 1];
__device__ int g_cursor[NNODES];
__device__ int g_sorted_src[EMAX];

__device__ __forceinline__ float lrelu(float x) {
    return x > 0.0f ? x : 0.2f * x;
}

// ---------------------------------------------------------------------------
// Conversions (weights + folded layer-2 attention vectors, one launch)
// ---------------------------------------------------------------------------
__global__ void cvt_f2h(const float* __restrict__ in, __half* __restrict__ out, int n4) {
    int i = blockIdx.x * blockDim.x + threadIdx.x;
    if (i >= n4) return;
    float4 v = *(const float4*)&in[i * 4];
    __half2 h0 = __floats2half2_rn(v.x, v.y);
    __half2 h1 = __floats2half2_rn(v.z, v.w);
    uint2 u;
    u.x = *(unsigned int*)&h0;
    u.y = *(unsigned int*)&h1;
    *(uint2*)&out[i * 4] = u;
}

__global__ void cvt_wts(const float* __restrict__ W1, __half* __restrict__ WT1,
                        const float* __restrict__ W2, __half* __restrict__ WT2,
                        const float* __restrict__ as2, const float* __restrict__ ad2,
                        float* __restrict__ wa2s, float* __restrict__ wa2d) {
    int i = blockIdx.x * blockDim.x + threadIdx.x;
    if (i < 128 * 128) {
        int n = i >> 7, k = i & 127;
        WT1[i] = __float2half(W1[k * 128 + n]);
    } else if (i < 128 * 128 + 256 * 128) {
        int j = i - 128 * 128;
        int n = j >> 7, k = j & 127;
        WT2[j] = __float2half(W2[k * 256 + n]);
    } else if (i < 128 * 128 + 256 * 128 + 128) {
        int k = i - (128 * 128 + 256 * 128);
        float s = 0.f, d = 0.f;
        #pragma unroll 8
        for (int c = 0; c < 256; c++) {
            float w = W2[k * 256 + c];
            s = fmaf(w, as2[c], s);
            d = fmaf(w, ad2[c], d);
        }
        wa2s[k] = s;
        wa2d[k] = d;
    }
}

// ---------------------------------------------------------------------------
// CSR build (vectorized; self-loops folded into scan).
// ---------------------------------------------------------------------------
__global__ void hist_dst_v(const int* __restrict__ ei, int E,
                           int* __restrict__ cnt) {
    int i = blockIdx.x * blockDim.x + threadIdx.x;
    int nv = E >> 2;
    if (i < nv) {
        int4 d4 = *(const int4*)&ei[E + i * 4];
        atomicAdd(&cnt[d4.x], 1);
        atomicAdd(&cnt[d4.y], 1);
        atomicAdd(&cnt[d4.z], 1);
        atomicAdd(&cnt[d4.w], 1);
    } else {
        int e = nv * 4 + (i - nv);
        if (e < E) atomicAdd(&cnt[ei[E + e]], 1);
    }
}

__global__ __launch_bounds__(1024, 1)
void scan_counts(const int* __restrict__ cnt, int* __restrict__ rowstart,
                 int* __restrict__ cursor, int N) {
    __shared__ int wsum[32];
    __shared__ int s_carry;
    const int tid = threadIdx.x, lane = tid & 31, wid = tid >> 5;
    if (tid == 0) s_carry = 0;
    __syncthreads();
    for (int base = 0; base < N; base += 4096) {
        int idx = base + tid * 4;
        int4 v = make_int4(-1, -1, -1, -1);
        if (idx + 3 < N) v = *(const int4*)&cnt[idx];
        else {
            if (idx + 0 < N) v.x = cnt[idx + 0];
            if (idx + 1 < N) v.y = cnt[idx + 1];
            if (idx + 2 < N) v.z = cnt[idx + 2];
            if (idx + 3 < N) v.w = cnt[idx + 3];
        }
        v.x += 1; v.y += 1; v.z += 1; v.w += 1;
        int tsum = v.x + v.y + v.z + v.w;
        int x = tsum;
        #pragma unroll
        for (int off = 1; off < 32; off <<= 1) {
            int y = __shfl_up_sync(0xFFFFFFFFu, x, off);
            if (lane >= off) x += y;
        }
        if (lane == 31) wsum[wid] = x;
        __syncthreads();
        if (wid == 0) {
            int w = wsum[lane];
            #pragma unroll
            for (int off = 1; off < 32; off <<= 1) {
                int y = __shfl_up_sync(0xFFFFFFFFu, w, off);
                if (lane >= off) w += y;
            }
            wsum[lane] = w;
        }
        __syncthreads();
        int carry = s_carry;
        int excl = carry + (wid > 0 ? wsum[wid - 1] : 0) + x - tsum;
        int e0 = excl, e1 = e0 + v.x, e2 = e1 + v.y, e3 = e2 + v.z;
        if (idx + 3 < N) {
            *(int4*)&rowstart[idx] = make_int4(e0, e1, e2, e3);
            *(int4*)&cursor[idx]   = make_int4(e0, e1, e2, e3);
        } else {
            if (idx + 0 < N) { rowstart[idx + 0] = e0; cursor[idx + 0] = e0; }
            if (idx + 1 < N) { rowstart[idx + 1] = e1; cursor[idx + 1] = e1; }
            if (idx + 2 < N) { rowstart[idx + 2] = e2; cursor[idx + 2] = e2; }
            if (idx + 3 < N) { rowstart[idx + 3] = e3; cursor[idx + 3] = e3; }
        }
        __syncthreads();
        if (tid == 1023) s_carry = carry + wsum[31];
        __syncthreads();
    }
    if (tid == 0) rowstart[N] = s_carry;
}

__global__ void scatter_edges_v(const int* __restrict__ ei, int E, int N,
                                int* __restrict__ cursor,
                                int* __restrict__ sorted_src) {
    int i = blockIdx.x * blockDim.x + threadIdx.x;
    int nv = E >> 2;
    if (i < nv) {
        int4 s4 = *(const int4*)&ei[i * 4];
        int4 d4 = *(const int4*)&ei[E + i * 4];
        int p0 = atomicAdd(&cursor[d4.x], 1);
        int p1 = atomicAdd(&cursor[d4.y], 1);
        int p2 = atomicAdd(&cursor[d4.z], 1);
        int p3 = atomicAdd(&cursor[d4.w], 1);
        sorted_src[p0] = s4.x;
        sorted_src[p1] = s4.y;
        sorted_src[p2] = s4.z;
        sorted_src[p3] = s4.w;
    } else if (i < nv + N) {
        int d = i - nv;
        int p = atomicAdd(&cursor[d], 1);
        sorted_src[p] = d;
    } else {
        int e = nv * 4 + (i - nv - N);
        if (e < E) {
            int s = ei[e], d = ei[E + e];
            int p = atomicAdd(&cursor[d], 1);
            sorted_src[p] = s;
        }
    }
}

// ---------------------------------------------------------------------------
// GEMM1 with fused node_alpha1 epilogue.
// Block 128x64, 8 warps (4M x 2N), warp tile 32x32; each warp's 32 cols are
// exactly one head -> per-row dot + quad shfl reduce, disjoint head writes.
// ---------------------------------------------------------------------------
#define AS_STRIDE 40
#define BS_STRIDE 136

__device__ __forceinline__ void mma16816(float* c, const unsigned int* a,
                                         unsigned int b0, unsigned int b1) {
    asm volatile(
        "mma.sync.aligned.m16n8k16.row.col.f32.f16.f16.f32 "
        "{%0,%1,%2,%3}, {%4,%5,%6,%7}, {%8,%9}, {%0,%1,%2,%3};"
        : "+f"(c[0]), "+f"(c[1]), "+f"(c[2]), "+f"(c[3])
        : "r"(a[0]), "r"(a[1]), "r"(a[2]), "r"(a[3]), "r"(b0), "r"(b1));
}

__global__ __launch_bounds__(256, 1)
void hgemm_a1(const __half* __restrict__ A, const __half* __restrict__ WT,
              const float* __restrict__ a_src, const float* __restrict__ a_dst,
              __half* __restrict__ C, float* __restrict__ als,
              float* __restrict__ ald, int M, int Ncols) {
    __shared__ __half As[128 * AS_STRIDE];
    __shared__ __half Bs[64 * BS_STRIDE];

    const int tid  = threadIdx.x;
    const int lane = tid & 31;
    const int wid  = tid >> 5;
    const int row0 = blockIdx.x * 128;
    const int col0 = blockIdx.y * 64;
    const int wm = (wid & 3) * 32;
    const int wn = (wid >> 2) * 32;

    {
        int n = tid >> 2;
        int p = (tid & 3) * 32;
        const uint4* src = (const uint4*)&WT[(size_t)(col0 + n) * 128 + p];
        uint4* dst = (uint4*)&Bs[n * BS_STRIDE + p];
        dst[0] = src[0]; dst[1] = src[1]; dst[2] = src[2]; dst[3] = src[3];
    }

    float acc[2][4][4];
    #pragma unroll
    for (int mt = 0; mt < 2; mt++)
        #pragma unroll
        for (int nt = 0; nt < 4; nt++)
            #pragma unroll
            for (int q = 0; q < 4; q++) acc[mt][nt][q] = 0.0f;

    const int arow = tid >> 1;
    const int acol = (tid & 1) * 16;
    const int frow = lane >> 2;
    const int fcol = 2 * (lane & 3);

    for (int kc = 0; kc < 128; kc += 32) {
        uint4 v0 = make_uint4(0, 0, 0, 0), v1 = make_uint4(0, 0, 0, 0);
        int gr = row0 + arow;
        if (gr < M) {
            const uint4* s = (const uint4*)&A[(size_t)gr * 128 + kc + acol];
            v0 = s[0]; v1 = s[1];
        }
        __syncthreads();
        *(uint4*)&As[arow * AS_STRIDE + acol]     = v0;
        *(uint4*)&As[arow * AS_STRIDE + acol + 8] = v1;
        __syncthreads();

        #pragma unroll
        for (int kk = 0; kk < 32; kk += 16) {
            unsigned int a[2][4];
            #pragma unroll
            for (int mt = 0; mt < 2; mt++) {
                int r = wm + mt * 16 + frow;
                int c = kk + fcol;
                a[mt][0] = *(const unsigned int*)&As[r * AS_STRIDE + c];
                a[mt][1] = *(const unsigned int*)&As[(r + 8) * AS_STRIDE + c];
                a[mt][2] = *(const unsigned int*)&As[r * AS_STRIDE + c + 8];
                a[mt][3] = *(const unsigned int*)&As[(r + 8) * AS_STRIDE + c + 8];
            }
            #pragma unroll
            for (int nt = 0; nt < 4; nt++) {
                int n = wn + nt * 8 + frow;
                int ck = kc + kk + fcol;
                unsigned int b0 = *(const unsigned int*)&Bs[n * BS_STRIDE + ck];
                unsigned int b1 = *(const unsigned int*)&Bs[n * BS_STRIDE + ck + 8];
                mma16816(acc[0][nt], a[0], b0, b1);
                mma16816(acc[1][nt], a[1], b0, b1);
            }
        }
    }

    // store C (fp16)
    #pragma unroll
    for (int mt = 0; mt < 2; mt++) {
        int r = row0 + wm + mt * 16 + frow;
        #pragma unroll
        for (int nt = 0; nt < 4; nt++) {
            int c = col0 + wn + nt * 8 + fcol;
            if (r < M) {
                __half2 h = __floats2half2_rn(acc[mt][nt][0], acc[mt][nt][1]);
                *(__half2*)&C[(size_t)r * Ncols + c] = h;
            }
            if (r + 8 < M) {
                __half2 h = __floats2half2_rn(acc[mt][nt][2], acc[mt][nt][3]);
                *(__half2*)&C[(size_t)(r + 8) * Ncols + c] = h;
            }
        }
    }

    // fused node_alpha1: this warp's 32 cols = head (col0+wn)>>5
    {
        const int head = (col0 + wn) >> 5;
        float ps[2][2] = {{0.f, 0.f}, {0.f, 0.f}};
        float pd[2][2] = {{0.f, 0.f}, {0.f, 0.f}};
        #pragma unroll
        for (int nt = 0; nt < 4; nt++) {
            int c = col0 + wn + nt * 8 + fcol;
            float2 sv = *(const float2*)&a_src[c];
            float2 dv = *(const float2*)&a_dst[c];
            #pragma unroll
            for (int mt = 0; mt < 2; mt++) {
                ps[mt][0] += acc[mt][nt][0] * sv.x + acc[mt][nt][1] * sv.y;
                ps[mt][1] += acc[mt][nt][2] * sv.x + acc[mt][nt][3] * sv.y;
                pd[mt][0] += acc[mt][nt][0] * dv.x + acc[mt][nt][1] * dv.y;
                pd[mt][1] += acc[mt][nt][2] * dv.x + acc[mt][nt][3] * dv.y;
            }
        }
        #pragma unroll
        for (int mt = 0; mt < 2; mt++)
            #pragma unroll
            for (int rs = 0; rs < 2; rs++) {
                float p = ps[mt][rs], qd = pd[mt][rs];
                p  += __shfl_xor_sync(0xFFFFFFFFu, p, 1);
                p  += __shfl_xor_sync(0xFFFFFFFFu, p, 2);
                qd += __shfl_xor_sync(0xFFFFFFFFu, qd, 1);
                qd += __shfl_xor_sync(0xFFFFFFFFu, qd, 2);
                if ((lane & 3) == 0) {
                    int r = row0 + wm + mt * 16 + rs * 8 + frow;
                    if (r < M) {
                        als[r * 4 + head] = p;
                        ald[r * 4 + head] = qd;
                    }
                }
            }
    }
}

// ---------------------------------------------------------------------------
// HGEMM (fp32 C + bias): layer-2 GEMM -> out.
// ---------------------------------------------------------------------------
__global__ __launch_bounds__(256, 1)
void hgemm_f32out(const __half* __restrict__ A, const __half* __restrict__ WT,
                  const float* __restrict__ bias, float* __restrict__ C,
                  int M, int Ncols) {
    __shared__ __half As[128 * AS_STRIDE];
    __shared__ __half Bs[64 * BS_STRIDE];

    const int tid  = threadIdx.x;
    const int lane = tid & 31;
    const int wid  = tid >> 5;
    const int row0 = blockIdx.x * 128;
    const int col0 = blockIdx.y * 64;
    const int wm = (wid & 3) * 32;
    const int wn = (wid >> 2) * 32;

    {
        int n = tid >> 2;
        int p = (tid & 3) * 32;
        const uint4* src = (const uint4*)&WT[(size_t)(col0 + n) * 128 + p];
        uint4* dst = (uint4*)&Bs[n * BS_STRIDE + p];
        dst[0] = src[0]; dst[1] = src[1]; dst[2] = src[2]; dst[3] = src[3];
    }

    float acc[2][4][4];
    #pragma unroll
    for (int mt = 0; mt < 2; mt++)
        #pragma unroll
        for (int nt = 0; nt < 4; nt++)
            #pragma unroll
            for (int q = 0; q < 4; q++) acc[mt][nt][q] = 0.0f;

    const int arow = tid >> 1;
    const int acol = (tid & 1) * 16;
    const int frow = lane >> 2;
    const int fcol = 2 * (lane & 3);

    for (int kc = 0; kc < 128; kc += 32) {
        uint4 v0 = make_uint4(0, 0, 0, 0), v1 = make_uint4(0, 0, 0, 0);
        int gr = row0 + arow;
        if (gr < M) {
            const uint4* s = (const uint4*)&A[(size_t)gr * 128 + kc + acol];
            v0 = s[0]; v1 = s[1];
        }
        __syncthreads();
        *(uint4*)&As[arow * AS_STRIDE + acol]     = v0;
        *(uint4*)&As[arow * AS_STRIDE + acol + 8] = v1;
        __syncthreads();

        #pragma unroll
        for (int kk = 0; kk < 32; kk += 16) {
            unsigned int a[2][4];
            #pragma unroll
            for (int mt = 0; mt < 2; mt++) {
                int r = wm + mt * 16 + frow;
                int c = kk + fcol;
                a[mt][0] = *(const unsigned int*)&As[r * AS_STRIDE + c];
                a[mt][1] = *(const unsigned int*)&As[(r + 8) * AS_STRIDE + c];
                a[mt][2] = *(const unsigned int*)&As[r * AS_STRIDE + c + 8];
                a[mt][3] = *(const unsigned int*)&As[(r + 8) * AS_STRIDE + c + 8];
            }
            #pragma unroll
            for (int nt = 0; nt < 4; nt++) {
                int n = wn + nt * 8 + frow;
                int ck = kc + kk + fcol;
                unsigned int b0 = *(const unsigned int*)&Bs[n * BS_STRIDE + ck];
                unsigned int b1 = *(const unsigned int*)&Bs[n * BS_STRIDE + ck + 8];
                mma16816(acc[0][nt], a[0], b0, b1);
                mma16816(acc[1][nt], a[1], b0, b1);
            }
        }
    }

    #pragma unroll
    for (int mt = 0; mt < 2; mt++) {
        int r = row0 + wm + mt * 16 + frow;
        #pragma unroll
        for (int nt = 0; nt < 4; nt++) {
            int c = col0 + wn + nt * 8 + fcol;
            float2 bb = *(const float2*)&bias[c];
            if (r < M) {
                float2 v = make_float2(acc[mt][nt][0] + bb.x, acc[mt][nt][1] + bb.y);
                *(float2*)&C[(size_t)r * Ncols + c] = v;
            }
            if (r + 8 < M) {
                float2 v = make_float2(acc[mt][nt][2] + bb.x, acc[mt][nt][3] + bb.y);
                *(float2*)&C[(size_t)(r + 8) * Ncols + c] = v;
            }
        }
    }
}

// ---------------------------------------------------------------------------
// Layer-1 gather + fused als2/ald2 epilogue. int4 ssrc, lane-parallel als +
// single exp + shfl bcast (R15 body). fp16 out, bias+relu.
// ---------------------------------------------------------------------------
__global__ __launch_bounds__(256)
void gather_agg1(const int* __restrict__ rowstart, const int* __restrict__ ssrc,
                 const float* __restrict__ als, const float* __restrict__ ald,
                 const __half* __restrict__ hlin, const float* __restrict__ bias,
                 const float* __restrict__ wa2s, const float* __restrict__ wa2d,
                 __half* __restrict__ outp, float* __restrict__ als2,
                 float* __restrict__ ald2, int N) {
    int w = (blockIdx.x * blockDim.x + threadIdx.x) >> 5;
    int lane = threadIdx.x & 31;
    if (w >= N) return;
    const int beg = rowstart[w];
    const int end = rowstart[w + 1];
    const int head = lane >> 3;
    const int q    = lane & 3;
    const int hsel = lane & 24;
    const float ad_h = ald[w * 4 + head];

    float ssum = 0.f;
    float4 acc = make_float4(0.f, 0.f, 0.f, 0.f);

    #define SCALAR_EDGE1(J)                                                    \
    {                                                                          \
        int sn = ssrc[J];                                                      \
        float e = __expf(lrelu(als[sn * 4 + head] + ad_h));                    \
        uint2 r = *(const uint2*)&hlin[(size_t)sn * 128 + lane * 4];           \
        ssum += e;                                                             \
        float2 a = __half22float2(*(const __half2*)&r.x);                      \
        float2 b = __half22float2(*(const __half2*)&r.y);                      \
        acc.x = fmaf(e, a.x, acc.x); acc.y = fmaf(e, a.y, acc.y);              \
        acc.z = fmaf(e, b.x, acc.z); acc.w = fmaf(e, b.y, acc.w);              \
    }

    int j = beg;
    int pro = (beg + 3) & ~3;
    if (pro > end) pro = end;
    for (; j < pro; j++) SCALAR_EDGE1(j)

    for (; j + 4 <= end; j += 4) {
        int4 sn4 = *(const int4*)&ssrc[j];
        int snq = (q == 0) ? sn4.x : (q == 1) ? sn4.y : (q == 2) ? sn4.z : sn4.w;
        float alv = als[snq * 4 + head];
        float ev = __expf(lrelu(alv + ad_h));
        float e0 = __shfl_sync(0xFFFFFFFFu, ev, hsel);
        float e1 = __shfl_sync(0xFFFFFFFFu, ev, hsel | 1);
        float e2 = __shfl_sync(0xFFFFFFFFu, ev, hsel | 2);
        float e3 = __shfl_sync(0xFFFFFFFFu, ev, hsel | 3);
        uint2 r0 = *(const uint2*)&hlin[(size_t)sn4.x * 128 + lane * 4];
        uint2 r1 = *(const uint2*)&hlin[(size_t)sn4.y * 128 + lane * 4];
        uint2 r2 = *(const uint2*)&hlin[(size_t)sn4.z * 128 + lane * 4];
        uint2 r3 = *(const uint2*)&hlin[(size_t)sn4.w * 128 + lane * 4];
        ssum += (e0 + e1) + (e2 + e3);
        float2 a, b;
        a = __half22float2(*(const __half2*)&r0.x);
        b = __half22float2(*(const __half2*)&r0.y);
        acc.x = fmaf(e0, a.x, acc.x); acc.y = fmaf(e0, a.y, acc.y);
        acc.z = fmaf(e0, b.x, acc.z); acc.w = fmaf(e0, b.y, acc.w);
        a = __half22float2(*(const __half2*)&r1.x);
        b = __half22float2(*(const __half2*)&r1.y);
        acc.x = fmaf(e1, a.x, acc.x); acc.y = fmaf(e1, a.y, acc.y);
        acc.z = fmaf(e1, b.x, acc.z); acc.w = fmaf(e1, b.y, acc.w);
        a = __half22float2(*(const __half2*)&r2.x);
        b = __half22float2(*(const __half2*)&r2.y);
        acc.x = fmaf(e2, a.x, acc.x); acc.y = fmaf(e2, a.y, acc.y);
        acc.z = fmaf(e2, b.x, acc.z); acc.w = fmaf(e2, b.y, acc.w);
        a = __half22float2(*(const __half2*)&r3.x);
        b = __half22float2(*(const __half2*)&r3.y);
        acc.x = fmaf(e3, a.x, acc.x); acc.y = fmaf(e3, a.y, acc.y);
        acc.z = fmaf(e3, b.x, acc.z); acc.w = fmaf(e3, b.y, acc.w);
    }
    for (; j < end; j++) SCALAR_EDGE1(j)
    #undef SCALAR_EDGE1

    const float inv = 1.0f / (ssum + 1e-16f);
    float4 bb = *(const float4*)&bias[lane * 4];
    acc.x = fmaxf(fmaf(acc.x, inv, bb.x), 0.f);
    acc.y = fmaxf(fmaf(acc.y, inv, bb.y), 0.f);
    acc.z = fmaxf(fmaf(acc.z, inv, bb.z), 0.f);
    acc.w = fmaxf(fmaf(acc.w, inv, bb.w), 0.f);
    __half2 h0 = __floats2half2_rn(acc.x, acc.y);
    __half2 h1 = __floats2half2_rn(acc.z, acc.w);
    uint2 u;
    u.x = *(unsigned int*)&h0;
    u.y = *(unsigned int*)&h1;
    *(uint2*)&outp[(size_t)w * 128 + lane * 4] = u;

    // fused als2/ald2 from fp32 aggregate
    float4 w2s = *(const float4*)&wa2s[lane * 4];
    float4 w2d = *(const float4*)&wa2d[lane * 4];
    float ps = acc.x * w2s.x + acc.y * w2s.y + acc.z * w2s.z + acc.w * w2s.w;
    float pd = acc.x * w2d.x + acc.y * w2d.y + acc.z * w2d.z + acc.w * w2d.w;
    #pragma unroll
    for (int off = 16; off > 0; off >>= 1) {
        ps += __shfl_xor_sync(0xFFFFFFFFu, ps, off);
        pd += __shfl_xor_sync(0xFFFFFFFFu, pd, off);
    }
    if (lane == 0) { als2[w] = ps; ald2[w] = pd; }
}

// ---------------------------------------------------------------------------
// Layer-2 gather of agg1 rows (R15 body). fp16 out.
// ---------------------------------------------------------------------------
__global__ __launch_bounds__(256)
void gather_h1(const int* __restrict__ rowstart, const int* __restrict__ ssrc,
               const float* __restrict__ als, const float* __restrict__ ald,
               const __half* __restrict__ h1, __half* __restrict__ outp, int N) {
    int w = (blockIdx.x * blockDim.x + threadIdx.x) >> 5;
    int lane = threadIdx.x & 31;
    if (w >= N) return;
    const int beg = rowstart[w];
    const int end = rowstart[w + 1];
    const int q   = lane & 3;
    const float ad = ald[w];

    float ssum = 0.f;
    float4 acc = make_float4(0.f, 0.f, 0.f, 0.f);

    #define SCALAR_EDGE2(J)                                                    \
    {                                                                          \
        int sn = ssrc[J];                                                      \
        float e = __expf(lrelu(als[sn] + ad));                                 \
        uint2 r = *(const uint2*)&h1[(size_t)sn * 128 + lane * 4];             \
        ssum += e;                                                             \
        float2 a = __half22float2(*(const __half2*)&r.x);                      \
        float2 b = __half22float2(*(const __half2*)&r.y);                      \
        acc.x = fmaf(e, a.x, acc.x); acc.y = fmaf(e, a.y, acc.y);              \
        acc.z = fmaf(e, b.x, acc.z); acc.w = fmaf(e, b.y, acc.w);              \
    }

    int j = beg;
    int pro = (beg + 3) & ~3;
    if (pro > end) pro = end;
    for (; j < pro; j++) SCALAR_EDGE2(j)

    for (; j + 4 <= end; j += 4) {
        int4 sn4 = *(const int4*)&ssrc[j];
        int snq = (q == 0) ? sn4.x : (q == 1) ? sn4.y : (q == 2) ? sn4.z : sn4.w;
        float alv = als[snq];
        float ev = __expf(lrelu(alv + ad));
        float e0 = __shfl_sync(0xFFFFFFFFu, ev, 0);
        float e1 = __shfl_sync(0xFFFFFFFFu, ev, 1);
        float e2 = __shfl_sync(0xFFFFFFFFu, ev, 2);
        float e3 = __shfl_sync(0xFFFFFFFFu, ev, 3);
        uint2 r0 = *(const uint2*)&h1[(size_t)sn4.x * 128 + lane * 4];
        uint2 r1 = *(const uint2*)&h1[(size_t)sn4.y * 128 + lane * 4];
        uint2 r2 = *(const uint2*)&h1[(size_t)sn4.z * 128 + lane * 4];
        uint2 r3 = *(const uint2*)&h1[(size_t)sn4.w * 128 + lane * 4];
        ssum += (e0 + e1) + (e2 + e3);
        float2 a, b;
        a = __half22float2(*(const __half2*)&r0.x);
        b = __half22float2(*(const __half2*)&r0.y);
        acc.x = fmaf(e0, a.x, acc.x); acc.y = fmaf(e0, a.y, acc.y);
        acc.z = fmaf(e0, b.x, acc.z); acc.w = fmaf(e0, b.y, acc.w);
        a = __half22float2(*(const __half2*)&r1.x);
        b = __half22float2(*(const __half2*)&r1.y);
        acc.x = fmaf(e1, a.x, acc.x); acc.y = fmaf(e1, a.y, acc.y);
        acc.z = fmaf(e1, b.x, acc.z); acc.w = fmaf(e1, b.y, acc.w);
        a = __half22float2(*(const __half2*)&r2.x);
        b = __half22float2(*(const __half2*)&r2.y);
        acc.x = fmaf(e2, a.x, acc.x); acc.y = fmaf(e2, a.y, acc.y);
        acc.z = fmaf(e2, b.x, acc.z); acc.w = fmaf(e2, b.y, acc.w);
        a = __half22float2(*(const __half2*)&r3.x);
        b = __half22float2(*(const __half2*)&r3.y);
        acc.x = fmaf(e3, a.x, acc.x); acc.y = fmaf(e3, a.y, acc.y);
        acc.z = fmaf(e3, b.x, acc.z); acc.w = fmaf(e3, b.y, acc.w);
    }
    for (; j < end; j++) SCALAR_EDGE2(j)
    #undef SCALAR_EDGE2

    const float inv = 1.0f / (ssum + 1e-16f);
    __half2 h0 = __floats2half2_rn(acc.x * inv, acc.y * inv);
    __half2 h1o = __floats2half2_rn(acc.z * inv, acc.w * inv);
    uint2 u;
    u.x = *(unsigned int*)&h0;
    u.y = *(unsigned int*)&h1o;
    *(uint2*)&outp[(size_t)w * 128 + lane * 4] = u;
}

// ---------------------------------------------------------------------------
// Launch
// ---------------------------------------------------------------------------
extern "C" void kernel_launch(void* const* d_in, const int* in_sizes, int n_in,
                              void* d_out, int out_size) {
    const float* x   = (const float*)d_in[0];
    const int*   ei  = (const int*)d_in[1];
    const float* W1  = (const float*)d_in[2];
    const float* as1 = (const float*)d_in[3];
    const float* ad1 = (const float*)d_in[4];
    const float* b1  = (const float*)d_in[5];
    const float* W2  = (const float*)d_in[6];
    const float* as2 = (const float*)d_in[7];
    const float* ad2 = (const float*)d_in[8];
    const float* b2  = (const float*)d_in[9];
    float* out = (float*)d_out;

    const int N = in_sizes[0] / 128;   // 50000
    const int E = in_sizes[1] / 2;     // 1600000

    float *wa2s, *wa2d, *als1p, *ald1p, *als2p, *ald2p;
    __half *xh, *wt1h, *wt2h, *hlin1, *agg1h, *agghx;
    int *cntp, *rowp, *curp, *ssrcp;
    cudaGetSymbolAddress((void**)&xh,    g_xh);
    cudaGetSymbolAddress((void**)&wt1h,  g_wt1h);
    cudaGetSymbolAddress((void**)&wt2h,  g_wt2h);
    cudaGetSymbolAddress((void**)&wa2s,  g_wa2s);
    cudaGetSymbolAddress((void**)&wa2d,  g_wa2d);
    cudaGetSymbolAddress((void**)&hlin1, g_hlin1);
    cudaGetSymbolAddress((void**)&als1p, g_als1);
    cudaGetSymbolAddress((void**)&ald1p, g_ald1);
    cudaGetSymbolAddress((void**)&agg1h, g_agg1h);
    cudaGetSymbolAddress((void**)&als2p, g_als2);
    cudaGetSymbolAddress((void**)&ald2p, g_ald2);
    cudaGetSymbolAddress((void**)&agghx, g_agghx);
    cudaGetSymbolAddress((void**)&cntp,  g_count);
    cudaGetSymbolAddress((void**)&rowp,  g_rowstart);
    cudaGetSymbolAddress((void**)&curp,  g_cursor);
    cudaGetSymbolAddress((void**)&ssrcp, g_sorted_src);

    static cudaStream_t s2 = nullptr;
    static cudaEvent_t ev_fork = nullptr, ev_csr = nullptr;
    if (s2 == nullptr) {
        cudaStreamCreateWithFlags(&s2, cudaStreamNonBlocking);
        cudaEventCreateWithFlags(&ev_fork, cudaEventDisableTiming);
        cudaEventCreateWithFlags(&ev_csr,  cudaEventDisableTiming);
    }

    const int NW_BLOCKS = (N * 32 + 255) / 256;
    const int HIST_THREADS = (E >> 2) + (E & 3);
    const int SCAT_THREADS = (E >> 2) + N + (E & 3);
    const int CVT_THREADS = 128 * 128 + 256 * 128 + 128;

    // --- fork: CSR build on s2 ---
    cudaEventRecord(ev_fork, 0);
    cudaStreamWaitEvent(s2, ev_fork, 0);
    cudaMemsetAsync(cntp, 0, (size_t)N * sizeof(int), s2);
    hist_dst_v<<<(HIST_THREADS + 255) / 256, 256, 0, s2>>>(ei, E, cntp);
    scan_counts<<<1, 1024, 0, s2>>>(cntp, rowp, curp, N);
    scatter_edges_v<<<(SCAT_THREADS + 255) / 256, 256, 0, s2>>>(ei, E, N, curp, ssrcp);
    cudaEventRecord(ev_csr, s2);

    // --- main: conversions + GEMM1(+alpha1) ---
    cvt_f2h<<<(N * 128 / 4 + 255) / 256, 256>>>(x, xh, N * 128 / 4);
    cvt_wts<<<(CVT_THREADS + 255) / 256, 256>>>(W1, wt1h, W2, wt2h,
                                                as2, ad2, wa2s, wa2d);
    {
        dim3 grid((N + 127) / 128, 2);
        hgemm_a1<<<grid, 256>>>(xh, wt1h, as1, ad1, hlin1, als1p, ald1p, N, 128);
    }

    // --- join CSR; gather1 (+fused als2) -> agg1h ---
    cudaStreamWaitEvent(0, ev_csr, 0);
    gather_agg1<<<NW_BLOCKS, 256>>>(rowp, ssrcp, als1p, ald1p, hlin1, b1,
                                    wa2s, wa2d, agg1h, als2p, ald2p, N);

    // --- layer 2: 128-dim gather -> GEMM2 (+bias) -> out ---
    gather_h1<<<NW_BLOCKS, 256>>>(rowp, ssrcp, als2p, ald2p, agg1h, agghx, N);
    {
        dim3 grid((N + 127) / 128, 4);
        hgemm_f32out<<<grid, 256>>>(agghx, wt2h, b2, out, N, 256);
    }
}